// round 3
// baseline (speedup 1.0000x reference)
#include <cuda_runtime.h>
#include <cuda_bf16.h>
#include <cstdint>

// ============================================================================
// NSFPRawMLP: x[262144,3] -> 128 -> (7x 128x128 + ReLU) -> 3
// mma.sync m16n8k16 bf16 / fp32 accum, split-GEMM (Ahi*Whi + Ahi*Wlo + Alo*Whi).
// R3: 512 thr / 256 rows per CTA (16 warps), triple-buffered weights (1 barrier
// per layer), p-pair interleaved MMA ordering for dependency spacing.
// ============================================================================

#define NROWS   262144
#define NHID    7
#define ROWS_PER_CTA 256
#define NTILES  (NROWS / ROWS_PER_CTA)   // 1024 CTAs
#define THREADS 512                      // 16 warps, 16 rows/warp

// Weight images: [layer][65536 B]: hi bf16 image at +0, lo at +32768.
// Image layout: byte = n*256 + ((chunk ^ (n&7))<<4) + (k&7)*2, chunk = k>>3.
static __device__ __align__(128) unsigned char g_wimg[NHID][65536];

// ---------------------------------------------------------------------------
// SMEM layout (dynamic): 3 weight buffers + small params
// ---------------------------------------------------------------------------
#define SM_WBUF    0                     // 3 x 65536 = 196608
#define SM_BIAS    196608                // 7*128 f32 = 3584
#define SM_W0      (SM_BIAS + 3584)      // 128*3 f32 = 1536
#define SM_B0      (SM_W0 + 1536)        // 128 f32  = 512
#define SM_WOUT    (SM_B0 + 512)         // 3*128 f32 = 1536
#define SM_BOUT    (SM_WOUT + 1536)      // 16
#define SMEM_SZ    (SM_BOUT + 16)        // 203,792 B

// ---------------------------------------------------------------------------
// PTX helpers (base-target, sm_80+)
// ---------------------------------------------------------------------------
__device__ __forceinline__ uint32_t smem_u32(const void* p) {
    uint32_t a;
    asm("{ .reg .u64 t; cvta.to.shared.u64 t, %1; cvt.u32.u64 %0, t; }"
        : "=r"(a) : "l"(p));
    return a;
}

#define CP_ASYNC16(dst_u32, src_ptr) \
    asm volatile("cp.async.cg.shared.global [%0], [%1], 16;" \
                 :: "r"(dst_u32), "l"(src_ptr) : "memory")
#define CP_COMMIT() asm volatile("cp.async.commit_group;" ::: "memory")
#define CP_WAIT(n)  asm volatile("cp.async.wait_group %0;" :: "n"(n) : "memory")

#define LDSM4(r0, r1, r2, r3, addr) \
    asm volatile("ldmatrix.sync.aligned.m8n8.x4.shared.b16 {%0,%1,%2,%3}, [%4];" \
                 : "=r"(r0), "=r"(r1), "=r"(r2), "=r"(r3) : "r"(addr))

#define MMA16816(C, A, b0_, b1_) \
    asm volatile("mma.sync.aligned.m16n8k16.row.col.f32.bf16.bf16.f32 " \
                 "{%0,%1,%2,%3},{%4,%5,%6,%7},{%8,%9},{%0,%1,%2,%3};" \
                 : "+f"((C)[0]), "+f"((C)[1]), "+f"((C)[2]), "+f"((C)[3]) \
                 : "r"((A)[0]), "r"((A)[1]), "r"((A)[2]), "r"((A)[3]), \
                   "r"(b0_), "r"(b1_))

// truncation split: v = hi(bf16 trunc) + lo(bf16 rn); packs a pair (v0 low).
__device__ __forceinline__ void split_pair(float v0, float v1,
                                           uint32_t& hi_pk, uint32_t& lo_pk) {
    uint32_t u0 = __float_as_uint(v0), u1 = __float_as_uint(v1);
    hi_pk = __byte_perm(u0, u1, 0x7632);          // {v1.hi16 : v0.hi16}
    float l0 = v0 - __uint_as_float(u0 & 0xFFFF0000u);
    float l1 = v1 - __uint_as_float(u1 & 0xFFFF0000u);
    asm("cvt.rn.bf16x2.f32 %0, %1, %2;" : "=r"(lo_pk) : "f"(l1), "f"(l0));
}

__device__ __forceinline__ float relu(float v) { return fmaxf(v, 0.0f); }

// ---------------------------------------------------------------------------
// Prep kernel: split Wh fp32 -> (hi,lo) bf16 into the swizzled image.
// ---------------------------------------------------------------------------
__global__ void prep_weights_kernel(const float* __restrict__ Wh) {
    int idx = blockIdx.x * blockDim.x + threadIdx.x;
    if (idx >= NHID * 128 * 128) return;
    int l = idx >> 14;
    int n = (idx >> 7) & 127;     // out feature
    int k = idx & 127;            // in feature
    float v = Wh[idx];
    uint32_t u = __float_as_uint(v);
    unsigned short hi = (unsigned short)(u >> 16);
    float lof = v - __uint_as_float(u & 0xFFFF0000u);
    __nv_bfloat16 lo = __float2bfloat16(lof);
    uint32_t chunk = (uint32_t)k >> 3;
    uint32_t off = (uint32_t)n * 256 + ((chunk ^ ((uint32_t)n & 7)) << 4)
                 + ((uint32_t)k & 7) * 2;
    *(unsigned short*)&g_wimg[l][off]         = hi;
    *(unsigned short*)&g_wimg[l][off + 32768] = *(unsigned short*)&lo;
}

// ---------------------------------------------------------------------------
// Main kernel
// ---------------------------------------------------------------------------
__global__ void __launch_bounds__(THREADS, 1)
mlp_kernel(const float* __restrict__ x,
           const float* __restrict__ W0,
           const float* __restrict__ b0,
           const float* __restrict__ bh,
           const float* __restrict__ Wout,
           const float* __restrict__ bout,
           float* __restrict__ out) {
    extern __shared__ char smem[];
    const uint32_t sb = smem_u32(smem);
    const int tid  = threadIdx.x;
    const int wid  = tid >> 5;
    const int lane = tid & 31;
    const int q    = lane & 3;          // quad index (col pair selector)

    // ---- kick off layer-0 weight prefetch immediately (buf 0) ----
    {
        const char* src = (const char*)&g_wimg[0][0];
        uint32_t dst = sb + SM_WBUF;
        #pragma unroll
        for (int i = 0; i < 8; i++)
            CP_ASYNC16(dst + (uint32_t)(tid + i * THREADS) * 16,
                       src + (size_t)(tid + i * THREADS) * 16);
        CP_COMMIT();
    }

    // ---- stage small params ----
    {
        float* bias_s = (float*)(smem + SM_BIAS);
        for (int i = tid; i < NHID * 128; i += THREADS) bias_s[i] = bh[i];
        if (tid < 128) {
            float* w0s = (float*)(smem + SM_W0);
            w0s[tid * 3 + 0] = W0[tid * 3 + 0];
            w0s[tid * 3 + 1] = W0[tid * 3 + 1];
            w0s[tid * 3 + 2] = W0[tid * 3 + 2];
            ((float*)(smem + SM_B0))[tid] = b0[tid];
        }
        if (tid >= 128 && tid < 512) ((float*)(smem + SM_WOUT))[tid - 128] = Wout[tid - 128];
        if (tid < 3) ((float*)(smem + SM_BOUT))[tid] = bout[tid];
    }
    __syncthreads();

    // global rows owned by this thread (2 per thread, m16 tile per warp)
    const int rbase = blockIdx.x * ROWS_PER_CTA + wid * 16 + (lane >> 2);
    const int g0 = rbase;        // row t/4
    const int g1 = rbase + 8;    // row t/4 + 8

    // ---- layer 0: [3 -> 128] in fp32 FFMA, produce A fragments ----
    uint32_t Ahi[8][4], Alo[8][4];
    {
        const float x00 = x[g0 * 3 + 0], x01 = x[g0 * 3 + 1], x02 = x[g0 * 3 + 2];
        const float x10 = x[g1 * 3 + 0], x11 = x[g1 * 3 + 1], x12 = x[g1 * 3 + 2];
        const float* w0s = (const float*)(smem + SM_W0);
        const float* b0s = (const float*)(smem + SM_B0);
        #pragma unroll
        for (int s = 0; s < 8; s++) {
            const int c0 = 16 * s + 2 * q;
            #pragma unroll
            for (int h = 0; h < 2; h++) {
                const int ca = c0 + 8 * h;
                const float wa0 = w0s[ca * 3 + 0], wa1 = w0s[ca * 3 + 1], wa2 = w0s[ca * 3 + 2];
                const float wb0 = w0s[(ca + 1) * 3 + 0], wb1 = w0s[(ca + 1) * 3 + 1], wb2 = w0s[(ca + 1) * 3 + 2];
                const float ba = b0s[ca], bb = b0s[ca + 1];
                float v00 = relu(fmaf(x00, wa0, fmaf(x01, wa1, fmaf(x02, wa2, ba))));
                float v01 = relu(fmaf(x00, wb0, fmaf(x01, wb1, fmaf(x02, wb2, bb))));
                float v10 = relu(fmaf(x10, wa0, fmaf(x11, wa1, fmaf(x12, wa2, ba))));
                float v11 = relu(fmaf(x10, wb0, fmaf(x11, wb1, fmaf(x12, wb2, bb))));
                split_pair(v00, v01, Ahi[s][2 * h + 0], Alo[s][2 * h + 0]);
                split_pair(v10, v11, Ahi[s][2 * h + 1], Alo[s][2 * h + 1]);
            }
        }
    }

    // per-thread ldmatrix address pieces
    const uint32_t nloc = (uint32_t)((lane & 7) + ((lane >> 4) & 1) * 8); // 0..15
    const uint32_t jbit = (uint32_t)((lane >> 3) & 1);                   // chunk +1
    uint32_t swz[8];
    #pragma unroll
    for (int s = 0; s < 8; s++)
        swz[s] = nloc * 256 + ((((uint32_t)(2 * s) + jbit) ^ (nloc & 7)) << 4);

    const float* bias_s = (const float*)(smem + SM_BIAS);
    const float* wout_s = (const float*)(smem + SM_WOUT);
    const float* bout_s = (const float*)(smem + SM_BOUT);

    // ---- 7 hidden layers, triple-buffered weights, ONE barrier per layer ----
    #pragma unroll 1
    for (int l = 0; l < NHID; l++) {
        // prefetch layer l+1 into buf[(l+1)%3] (buf[(l-2)%3]: nobody reads it)
        if (l + 1 < NHID) {
            const char* src = (const char*)&g_wimg[l + 1][0];
            uint32_t dst = sb + SM_WBUF + (uint32_t)((l + 1) % 3) * 65536;
            #pragma unroll
            for (int i = 0; i < 8; i++)
                CP_ASYNC16(dst + (uint32_t)(tid + i * THREADS) * 16,
                           src + (size_t)(tid + i * THREADS) * 16);
            CP_COMMIT();
            CP_WAIT(1);            // buf[l%3] group complete
        } else {
            CP_WAIT(0);
        }
        __syncthreads();           // visibility of buf[l%3] across threads

        const uint32_t wb = sb + SM_WBUF + (uint32_t)(l % 3) * 65536;

        float C[16][4];
        #pragma unroll
        for (int g = 0; g < 16; g++)
            { C[g][0] = 0.f; C[g][1] = 0.f; C[g][2] = 0.f; C[g][3] = 0.f; }

        #pragma unroll
        for (int s = 0; s < 8; s++) {
            const uint32_t base = wb + swz[s];
            #pragma unroll
            for (int pp = 0; pp < 4; pp++) {     // p-pairs: 4 independent C regs
                const uint32_t a0 = base + (uint32_t)(2 * pp) * 4096;
                const uint32_t a1 = a0 + 4096;
                uint32_t h0, h1, h2, h3, h4, h5, h6, h7;
                uint32_t w0_, w1_, w2_, w3_, w4_, w5_, w6_, w7_;
                LDSM4(h0, h1, h2, h3, a0);            // Whi p=2pp
                LDSM4(h4, h5, h6, h7, a1);            // Whi p=2pp+1
                LDSM4(w0_, w1_, w2_, w3_, a0 + 32768); // Wlo p=2pp
                LDSM4(w4_, w5_, w6_, w7_, a1 + 32768); // Wlo p=2pp+1
                float* C0 = C[4 * pp + 0];
                float* C1 = C[4 * pp + 1];
                float* C2 = C[4 * pp + 2];
                float* C3 = C[4 * pp + 3];
                MMA16816(C0, Ahi[s], h0, h1);
                MMA16816(C1, Ahi[s], h2, h3);
                MMA16816(C2, Ahi[s], h4, h5);
                MMA16816(C3, Ahi[s], h6, h7);
                MMA16816(C0, Alo[s], h0, h1);
                MMA16816(C1, Alo[s], h2, h3);
                MMA16816(C2, Alo[s], h4, h5);
                MMA16816(C3, Alo[s], h6, h7);
                MMA16816(C0, Ahi[s], w0_, w1_);
                MMA16816(C1, Ahi[s], w2_, w3_);
                MMA16816(C2, Ahi[s], w4_, w5_);
                MMA16816(C3, Ahi[s], w6_, w7_);
            }
        }

        const float* bl = bias_s + l * 128;

        if (l < NHID - 1) {
            // bias + relu + split -> next layer A fragments
            #pragma unroll
            for (int s = 0; s < 8; s++) {
                const float2 bb0 = *(const float2*)&bl[16 * s + 2 * q];
                const float2 bb1 = *(const float2*)&bl[16 * s + 8 + 2 * q];
                float v00 = relu(C[2 * s][0] + bb0.x);
                float v01 = relu(C[2 * s][1] + bb0.y);
                float v10 = relu(C[2 * s][2] + bb0.x);
                float v11 = relu(C[2 * s][3] + bb0.y);
                split_pair(v00, v01, Ahi[s][0], Alo[s][0]);
                split_pair(v10, v11, Ahi[s][1], Alo[s][1]);
                float w00 = relu(C[2 * s + 1][0] + bb1.x);
                float w01 = relu(C[2 * s + 1][1] + bb1.y);
                float w10 = relu(C[2 * s + 1][2] + bb1.x);
                float w11 = relu(C[2 * s + 1][3] + bb1.y);
                split_pair(w00, w01, Ahi[s][2], Alo[s][2]);
                split_pair(w10, w11, Ahi[s][3], Alo[s][3]);
            }
        } else {
            // final: bias + relu, fused [128 -> 3] projection + bout
            float o00 = 0.f, o01 = 0.f, o02 = 0.f;   // row g0
            float o10 = 0.f, o11 = 0.f, o12 = 0.f;   // row g1
            #pragma unroll
            for (int g = 0; g < 16; g++) {
                const int c = 8 * g + 2 * q;
                const float2 bb = *(const float2*)&bl[c];
                float v00 = relu(C[g][0] + bb.x);
                float v01 = relu(C[g][1] + bb.y);
                float v10 = relu(C[g][2] + bb.x);
                float v11 = relu(C[g][3] + bb.y);
                const float2 wj0 = *(const float2*)&wout_s[0 * 128 + c];
                const float2 wj1 = *(const float2*)&wout_s[1 * 128 + c];
                const float2 wj2 = *(const float2*)&wout_s[2 * 128 + c];
                o00 = fmaf(v00, wj0.x, fmaf(v01, wj0.y, o00));
                o01 = fmaf(v00, wj1.x, fmaf(v01, wj1.y, o01));
                o02 = fmaf(v00, wj2.x, fmaf(v01, wj2.y, o02));
                o10 = fmaf(v10, wj0.x, fmaf(v11, wj0.y, o10));
                o11 = fmaf(v10, wj1.x, fmaf(v11, wj1.y, o11));
                o12 = fmaf(v10, wj2.x, fmaf(v11, wj2.y, o12));
            }
            #pragma unroll
            for (int d = 1; d <= 2; d <<= 1) {
                o00 += __shfl_xor_sync(0xFFFFFFFF, o00, d);
                o01 += __shfl_xor_sync(0xFFFFFFFF, o01, d);
                o02 += __shfl_xor_sync(0xFFFFFFFF, o02, d);
                o10 += __shfl_xor_sync(0xFFFFFFFF, o10, d);
                o11 += __shfl_xor_sync(0xFFFFFFFF, o11, d);
                o12 += __shfl_xor_sync(0xFFFFFFFF, o12, d);
            }
            if (q == 0) {
                out[g0 * 3 + 0] = o00 + bout_s[0];
                out[g0 * 3 + 1] = o01 + bout_s[1];
                out[g0 * 3 + 2] = o02 + bout_s[2];
                out[g1 * 3 + 0] = o10 + bout_s[0];
                out[g1 * 3 + 1] = o11 + bout_s[1];
                out[g1 * 3 + 2] = o12 + bout_s[2];
            }
        }
    }
}

// ---------------------------------------------------------------------------
// kernel_launch
// ---------------------------------------------------------------------------
extern "C" void kernel_launch(void* const* d_in, const int* in_sizes, int n_in,
                              void* d_out, int out_size) {
    const float* x    = (const float*)d_in[0];   // [262144,3]
    const float* W0   = (const float*)d_in[1];   // [128,3]
    const float* b0   = (const float*)d_in[2];   // [128]
    const float* Wh   = (const float*)d_in[3];   // [7,128,128]
    const float* bh   = (const float*)d_in[4];   // [7,128]
    const float* Wout = (const float*)d_in[5];   // [3,128]
    const float* bout = (const float*)d_in[6];   // [3]
    float* out = (float*)d_out;                  // [262144,3]

    static bool attr_set = false;
    if (!attr_set) {
        cudaFuncSetAttribute(mlp_kernel,
                             cudaFuncAttributeMaxDynamicSharedMemorySize, SMEM_SZ);
        attr_set = true;
    }

    prep_weights_kernel<<<(NHID * 128 * 128 + 255) / 256, 256>>>(Wh);
    mlp_kernel<<<NTILES, THREADS, SMEM_SZ>>>(x, W0, b0, bh, Wout, bout, out);
}

// round 4
// speedup vs baseline: 1.0487x; 1.0487x over previous
#include <cuda_runtime.h>
#include <cuda_bf16.h>
#include <cstdint>

// ============================================================================
// NSFPRawMLP: x[262144,3] -> 128 -> (7x 128x128 + ReLU) -> 3
// mma.sync m16n8k16 bf16 / fp32 accum, split-GEMM (Ahi*Whi + Ahi*Wlo + Alo*Whi).
// R4: 256 thr / 128 rows (spill-free, 202+ regs OK) + p-pair interleaved MMA
// ordering + triple-buffered weights with depth-2 cp.async prefetch.
// ============================================================================

#define NROWS   262144
#define NHID    7
#define ROWS_PER_CTA 128
#define NTILES  (NROWS / ROWS_PER_CTA)   // 2048 CTAs
#define THREADS 256                      // 8 warps, 16 rows/warp

// Weight images: [layer][65536 B]: hi bf16 image at +0, lo at +32768.
// Image layout: byte = n*256 + ((chunk ^ (n&7))<<4) + (k&7)*2, chunk = k>>3.
static __device__ __align__(128) unsigned char g_wimg[NHID][65536];

// ---------------------------------------------------------------------------
// SMEM layout (dynamic): 3 weight buffers + small params
// ---------------------------------------------------------------------------
#define SM_WBUF    0                     // 3 x 65536 = 196608
#define SM_BIAS    196608                // 7*128 f32 = 3584
#define SM_W0      (SM_BIAS + 3584)      // 128*3 f32 = 1536
#define SM_B0      (SM_W0 + 1536)        // 128 f32  = 512
#define SM_WOUT    (SM_B0 + 512)         // 3*128 f32 = 1536
#define SM_BOUT    (SM_WOUT + 1536)      // 16
#define SMEM_SZ    (SM_BOUT + 16)        // 203,792 B

// ---------------------------------------------------------------------------
// PTX helpers (base-target, sm_80+)
// ---------------------------------------------------------------------------
__device__ __forceinline__ uint32_t smem_u32(const void* p) {
    uint32_t a;
    asm("{ .reg .u64 t; cvta.to.shared.u64 t, %1; cvt.u32.u64 %0, t; }"
        : "=r"(a) : "l"(p));
    return a;
}

#define CP_ASYNC16(dst_u32, src_ptr) \
    asm volatile("cp.async.cg.shared.global [%0], [%1], 16;" \
                 :: "r"(dst_u32), "l"(src_ptr) : "memory")
#define CP_COMMIT() asm volatile("cp.async.commit_group;" ::: "memory")
#define CP_WAIT(n)  asm volatile("cp.async.wait_group %0;" :: "n"(n) : "memory")

#define LDSM4(r0, r1, r2, r3, addr) \
    asm volatile("ldmatrix.sync.aligned.m8n8.x4.shared.b16 {%0,%1,%2,%3}, [%4];" \
                 : "=r"(r0), "=r"(r1), "=r"(r2), "=r"(r3) : "r"(addr))

#define MMA16816(C, A, b0_, b1_) \
    asm volatile("mma.sync.aligned.m16n8k16.row.col.f32.bf16.bf16.f32 " \
                 "{%0,%1,%2,%3},{%4,%5,%6,%7},{%8,%9},{%0,%1,%2,%3};" \
                 : "+f"((C)[0]), "+f"((C)[1]), "+f"((C)[2]), "+f"((C)[3]) \
                 : "r"((A)[0]), "r"((A)[1]), "r"((A)[2]), "r"((A)[3]), \
                   "r"(b0_), "r"(b1_))

// truncation split: v = hi(bf16 trunc) + lo(bf16 rn); packs a pair (v0 low).
__device__ __forceinline__ void split_pair(float v0, float v1,
                                           uint32_t& hi_pk, uint32_t& lo_pk) {
    uint32_t u0 = __float_as_uint(v0), u1 = __float_as_uint(v1);
    hi_pk = __byte_perm(u0, u1, 0x7632);          // {v1.hi16 : v0.hi16}
    float l0 = v0 - __uint_as_float(u0 & 0xFFFF0000u);
    float l1 = v1 - __uint_as_float(u1 & 0xFFFF0000u);
    asm("cvt.rn.bf16x2.f32 %0, %1, %2;" : "=r"(lo_pk) : "f"(l1), "f"(l0));
}

__device__ __forceinline__ float relu(float v) { return fmaxf(v, 0.0f); }

// ---------------------------------------------------------------------------
// Prep kernel: split Wh fp32 -> (hi,lo) bf16 into the swizzled image.
// ---------------------------------------------------------------------------
__global__ void prep_weights_kernel(const float* __restrict__ Wh) {
    int idx = blockIdx.x * blockDim.x + threadIdx.x;
    if (idx >= NHID * 128 * 128) return;
    int l = idx >> 14;
    int n = (idx >> 7) & 127;     // out feature
    int k = idx & 127;            // in feature
    float v = Wh[idx];
    uint32_t u = __float_as_uint(v);
    unsigned short hi = (unsigned short)(u >> 16);
    float lof = v - __uint_as_float(u & 0xFFFF0000u);
    __nv_bfloat16 lo = __float2bfloat16(lof);
    uint32_t chunk = (uint32_t)k >> 3;
    uint32_t off = (uint32_t)n * 256 + ((chunk ^ ((uint32_t)n & 7)) << 4)
                 + ((uint32_t)k & 7) * 2;
    *(unsigned short*)&g_wimg[l][off]         = hi;
    *(unsigned short*)&g_wimg[l][off + 32768] = *(unsigned short*)&lo;
}

// issue cp.async prefetch of one 64KB layer image into buf[layer%3]
__device__ __forceinline__ void prefetch_layer(uint32_t sb, int layer, int tid) {
    const char* src = (const char*)&g_wimg[layer][0];
    uint32_t dst = sb + SM_WBUF + (uint32_t)(layer % 3) * 65536;
    #pragma unroll
    for (int i = 0; i < 16; i++)
        CP_ASYNC16(dst + (uint32_t)(tid + i * THREADS) * 16,
                   src + (size_t)(tid + i * THREADS) * 16);
    CP_COMMIT();
}

// ---------------------------------------------------------------------------
// Main kernel
// ---------------------------------------------------------------------------
__global__ void __launch_bounds__(THREADS, 1)
mlp_kernel(const float* __restrict__ x,
           const float* __restrict__ W0,
           const float* __restrict__ b0,
           const float* __restrict__ bh,
           const float* __restrict__ Wout,
           const float* __restrict__ bout,
           float* __restrict__ out) {
    extern __shared__ char smem[];
    const uint32_t sb = smem_u32(smem);
    const int tid  = threadIdx.x;
    const int wid  = tid >> 5;
    const int lane = tid & 31;
    const int q    = lane & 3;          // quad index (col pair selector)

    // ---- depth-2 prefetch: layers 0 and 1 in flight before any compute ----
    prefetch_layer(sb, 0, tid);
    prefetch_layer(sb, 1, tid);

    // ---- stage small params ----
    {
        float* bias_s = (float*)(smem + SM_BIAS);
        for (int i = tid; i < NHID * 128; i += THREADS) bias_s[i] = bh[i];
        if (tid < 128) {
            float* w0s = (float*)(smem + SM_W0);
            w0s[tid * 3 + 0] = W0[tid * 3 + 0];
            w0s[tid * 3 + 1] = W0[tid * 3 + 1];
            w0s[tid * 3 + 2] = W0[tid * 3 + 2];
            ((float*)(smem + SM_B0))[tid] = b0[tid];
        }
        float* wos = (float*)(smem + SM_WOUT);
        for (int i = tid; i < 384; i += THREADS) wos[i] = Wout[i];
        if (tid < 3) ((float*)(smem + SM_BOUT))[tid] = bout[tid];
    }
    __syncthreads();

    // global rows owned by this thread (2 per thread, m16 tile per warp)
    const int rbase = blockIdx.x * ROWS_PER_CTA + wid * 16 + (lane >> 2);
    const int g0 = rbase;        // row t/4
    const int g1 = rbase + 8;    // row t/4 + 8

    // ---- layer 0: [3 -> 128] in fp32 FFMA, produce A fragments ----
    uint32_t Ahi[8][4], Alo[8][4];
    {
        const float x00 = x[g0 * 3 + 0], x01 = x[g0 * 3 + 1], x02 = x[g0 * 3 + 2];
        const float x10 = x[g1 * 3 + 0], x11 = x[g1 * 3 + 1], x12 = x[g1 * 3 + 2];
        const float* w0s = (const float*)(smem + SM_W0);
        const float* b0s = (const float*)(smem + SM_B0);
        #pragma unroll
        for (int s = 0; s < 8; s++) {
            const int c0 = 16 * s + 2 * q;
            #pragma unroll
            for (int h = 0; h < 2; h++) {
                const int ca = c0 + 8 * h;
                const float wa0 = w0s[ca * 3 + 0], wa1 = w0s[ca * 3 + 1], wa2 = w0s[ca * 3 + 2];
                const float wb0 = w0s[(ca + 1) * 3 + 0], wb1 = w0s[(ca + 1) * 3 + 1], wb2 = w0s[(ca + 1) * 3 + 2];
                const float ba = b0s[ca], bb = b0s[ca + 1];
                float v00 = relu(fmaf(x00, wa0, fmaf(x01, wa1, fmaf(x02, wa2, ba))));
                float v01 = relu(fmaf(x00, wb0, fmaf(x01, wb1, fmaf(x02, wb2, bb))));
                float v10 = relu(fmaf(x10, wa0, fmaf(x11, wa1, fmaf(x12, wa2, ba))));
                float v11 = relu(fmaf(x10, wb0, fmaf(x11, wb1, fmaf(x12, wb2, bb))));
                split_pair(v00, v01, Ahi[s][2 * h + 0], Alo[s][2 * h + 0]);
                split_pair(v10, v11, Ahi[s][2 * h + 1], Alo[s][2 * h + 1]);
            }
        }
    }

    // per-thread ldmatrix address pieces
    const uint32_t nloc = (uint32_t)((lane & 7) + ((lane >> 4) & 1) * 8); // 0..15
    const uint32_t jbit = (uint32_t)((lane >> 3) & 1);                   // chunk +1
    uint32_t swz[8];
    #pragma unroll
    for (int s = 0; s < 8; s++)
        swz[s] = nloc * 256 + ((((uint32_t)(2 * s) + jbit) ^ (nloc & 7)) << 4);

    const float* bias_s = (const float*)(smem + SM_BIAS);
    const float* wout_s = (const float*)(smem + SM_WOUT);
    const float* bout_s = (const float*)(smem + SM_BOUT);

    // ---- 7 hidden layers, triple-buffered weights, depth-2 prefetch ----
    #pragma unroll 1
    for (int l = 0; l < NHID; l++) {
        // all warps finished reading buf[(l-1)%3] == buf[(l+2)%3] -> safe to refill
        __syncthreads();
        if (l + 2 < NHID) prefetch_layer(sb, l + 2, tid);
        // ensure groups <= l are complete (pending allowed: l+1, l+2 if committed)
        if (l <= NHID - 3)      CP_WAIT(2);
        else if (l == NHID - 2) CP_WAIT(1);
        else                    CP_WAIT(0);
        __syncthreads();           // cross-thread visibility of buf[l%3]

        const uint32_t wb = sb + SM_WBUF + (uint32_t)(l % 3) * 65536;

        float C[16][4];
        #pragma unroll
        for (int g = 0; g < 16; g++)
            { C[g][0] = 0.f; C[g][1] = 0.f; C[g][2] = 0.f; C[g][3] = 0.f; }

        #pragma unroll
        for (int s = 0; s < 8; s++) {
            const uint32_t base = wb + swz[s];
            #pragma unroll
            for (int pp = 0; pp < 4; pp++) {     // p-pairs: 4 independent C regs
                const uint32_t a0 = base + (uint32_t)(2 * pp) * 4096;
                const uint32_t a1 = a0 + 4096;
                uint32_t h0, h1, h2, h3, h4, h5, h6, h7;
                uint32_t w0_, w1_, w2_, w3_, w4_, w5_, w6_, w7_;
                LDSM4(h0, h1, h2, h3, a0);             // Whi p=2pp
                LDSM4(h4, h5, h6, h7, a1);             // Whi p=2pp+1
                LDSM4(w0_, w1_, w2_, w3_, a0 + 32768); // Wlo p=2pp
                LDSM4(w4_, w5_, w6_, w7_, a1 + 32768); // Wlo p=2pp+1
                float* C0 = C[4 * pp + 0];
                float* C1 = C[4 * pp + 1];
                float* C2 = C[4 * pp + 2];
                float* C3 = C[4 * pp + 3];
                MMA16816(C0, Ahi[s], h0, h1);
                MMA16816(C1, Ahi[s], h2, h3);
                MMA16816(C2, Ahi[s], h4, h5);
                MMA16816(C3, Ahi[s], h6, h7);
                MMA16816(C0, Alo[s], h0, h1);
                MMA16816(C1, Alo[s], h2, h3);
                MMA16816(C2, Alo[s], h4, h5);
                MMA16816(C3, Alo[s], h6, h7);
                MMA16816(C0, Ahi[s], w0_, w1_);
                MMA16816(C1, Ahi[s], w2_, w3_);
                MMA16816(C2, Ahi[s], w4_, w5_);
                MMA16816(C3, Ahi[s], w6_, w7_);
            }
        }

        const float* bl = bias_s + l * 128;

        if (l < NHID - 1) {
            // bias + relu + split -> next layer A fragments
            #pragma unroll
            for (int s = 0; s < 8; s++) {
                const float2 bb0 = *(const float2*)&bl[16 * s + 2 * q];
                const float2 bb1 = *(const float2*)&bl[16 * s + 8 + 2 * q];
                float v00 = relu(C[2 * s][0] + bb0.x);
                float v01 = relu(C[2 * s][1] + bb0.y);
                float v10 = relu(C[2 * s][2] + bb0.x);
                float v11 = relu(C[2 * s][3] + bb0.y);
                split_pair(v00, v01, Ahi[s][0], Alo[s][0]);
                split_pair(v10, v11, Ahi[s][1], Alo[s][1]);
                float w00 = relu(C[2 * s + 1][0] + bb1.x);
                float w01 = relu(C[2 * s + 1][1] + bb1.y);
                float w10 = relu(C[2 * s + 1][2] + bb1.x);
                float w11 = relu(C[2 * s + 1][3] + bb1.y);
                split_pair(w00, w01, Ahi[s][2], Alo[s][2]);
                split_pair(w10, w11, Ahi[s][3], Alo[s][3]);
            }
        } else {
            // final: bias + relu, fused [128 -> 3] projection + bout
            float o00 = 0.f, o01 = 0.f, o02 = 0.f;   // row g0
            float o10 = 0.f, o11 = 0.f, o12 = 0.f;   // row g1
            #pragma unroll
            for (int g = 0; g < 16; g++) {
                const int c = 8 * g + 2 * q;
                const float2 bb = *(const float2*)&bl[c];
                float v00 = relu(C[g][0] + bb.x);
                float v01 = relu(C[g][1] + bb.y);
                float v10 = relu(C[g][2] + bb.x);
                float v11 = relu(C[g][3] + bb.y);
                const float2 wj0 = *(const float2*)&wout_s[0 * 128 + c];
                const float2 wj1 = *(const float2*)&wout_s[1 * 128 + c];
                const float2 wj2 = *(const float2*)&wout_s[2 * 128 + c];
                o00 = fmaf(v00, wj0.x, fmaf(v01, wj0.y, o00));
                o01 = fmaf(v00, wj1.x, fmaf(v01, wj1.y, o01));
                o02 = fmaf(v00, wj2.x, fmaf(v01, wj2.y, o02));
                o10 = fmaf(v10, wj0.x, fmaf(v11, wj0.y, o10));
                o11 = fmaf(v10, wj1.x, fmaf(v11, wj1.y, o11));
                o12 = fmaf(v10, wj2.x, fmaf(v11, wj2.y, o12));
            }
            #pragma unroll
            for (int d = 1; d <= 2; d <<= 1) {
                o00 += __shfl_xor_sync(0xFFFFFFFF, o00, d);
                o01 += __shfl_xor_sync(0xFFFFFFFF, o01, d);
                o02 += __shfl_xor_sync(0xFFFFFFFF, o02, d);
                o10 += __shfl_xor_sync(0xFFFFFFFF, o10, d);
                o11 += __shfl_xor_sync(0xFFFFFFFF, o11, d);
                o12 += __shfl_xor_sync(0xFFFFFFFF, o12, d);
            }
            if (q == 0) {
                out[g0 * 3 + 0] = o00 + bout_s[0];
                out[g0 * 3 + 1] = o01 + bout_s[1];
                out[g0 * 3 + 2] = o02 + bout_s[2];
                out[g1 * 3 + 0] = o10 + bout_s[0];
                out[g1 * 3 + 1] = o11 + bout_s[1];
                out[g1 * 3 + 2] = o12 + bout_s[2];
            }
        }
    }
}

// ---------------------------------------------------------------------------
// kernel_launch
// ---------------------------------------------------------------------------
extern "C" void kernel_launch(void* const* d_in, const int* in_sizes, int n_in,
                              void* d_out, int out_size) {
    const float* x    = (const float*)d_in[0];   // [262144,3]
    const float* W0   = (const float*)d_in[1];   // [128,3]
    const float* b0   = (const float*)d_in[2];   // [128]
    const float* Wh   = (const float*)d_in[3];   // [7,128,128]
    const float* bh   = (const float*)d_in[4];   // [7,128]
    const float* Wout = (const float*)d_in[5];   // [3,128]
    const float* bout = (const float*)d_in[6];   // [3]
    float* out = (float*)d_out;                  // [262144,3]

    static bool attr_set = false;
    if (!attr_set) {
        cudaFuncSetAttribute(mlp_kernel,
                             cudaFuncAttributeMaxDynamicSharedMemorySize, SMEM_SZ);
        attr_set = true;
    }

    prep_weights_kernel<<<(NHID * 128 * 128 + 255) / 256, 256>>>(Wh);
    mlp_kernel<<<NTILES, THREADS, SMEM_SZ>>>(x, W0, b0, bh, Wout, bout, out);
}

// round 5
// speedup vs baseline: 1.1529x; 1.0993x over previous
#include <cuda_runtime.h>
#include <cuda_bf16.h>
#include <cstdint>

// ============================================================================
// NSFPRawMLP: x[262144,3] -> 128 -> (7x 128x128 + ReLU) -> 3
// mma.sync m16n8k16 bf16 / fp32 accum, split-GEMM (Ahi*Whi + Ahi*Wlo + Alo*Whi).
// R5: 128 thr / 64 rows per CTA, 2 CTAs per SM (51.7K regs, 145KB smem) so the
// per-layer epilogue+barrier bubble of one CTA is covered by the other CTA's
// MMAs. Single-buffered weights; cp.async for layer l+1 issued before the
// epilogue of layer l (hidden behind epilogue + other CTA).
// ============================================================================

#define NROWS   262144
#define NHID    7
#define ROWS_PER_CTA 64
#define NTILES  (NROWS / ROWS_PER_CTA)   // 4096 CTAs
#define THREADS 128                      // 4 warps, 16 rows/warp

// Weight images: [layer][65536 B]: hi bf16 image at +0, lo at +32768.
// Image layout: byte = n*256 + ((chunk ^ (n&7))<<4) + (k&7)*2, chunk = k>>3.
static __device__ __align__(128) unsigned char g_wimg[NHID][65536];

// ---------------------------------------------------------------------------
// SMEM layout (dynamic): ONE weight buffer + small params  (~72.7KB -> 2 CTA/SM)
// ---------------------------------------------------------------------------
#define SM_WBUF    0                     // 65536
#define SM_BIAS    65536                 // 7*128 f32 = 3584
#define SM_W0      (SM_BIAS + 3584)      // 128*3 f32 = 1536
#define SM_B0      (SM_W0 + 1536)        // 128 f32  = 512
#define SM_WOUT    (SM_B0 + 512)         // 3*128 f32 = 1536
#define SM_BOUT    (SM_WOUT + 1536)      // 16
#define SMEM_SZ    (SM_BOUT + 16)        // 72,720 B

// ---------------------------------------------------------------------------
// PTX helpers (base-target, sm_80+)
// ---------------------------------------------------------------------------
__device__ __forceinline__ uint32_t smem_u32(const void* p) {
    uint32_t a;
    asm("{ .reg .u64 t; cvta.to.shared.u64 t, %1; cvt.u32.u64 %0, t; }"
        : "=r"(a) : "l"(p));
    return a;
}

#define CP_ASYNC16(dst_u32, src_ptr) \
    asm volatile("cp.async.cg.shared.global [%0], [%1], 16;" \
                 :: "r"(dst_u32), "l"(src_ptr) : "memory")
#define CP_COMMIT() asm volatile("cp.async.commit_group;" ::: "memory")
#define CP_WAIT(n)  asm volatile("cp.async.wait_group %0;" :: "n"(n) : "memory")

#define LDSM4(r0, r1, r2, r3, addr) \
    asm volatile("ldmatrix.sync.aligned.m8n8.x4.shared.b16 {%0,%1,%2,%3}, [%4];" \
                 : "=r"(r0), "=r"(r1), "=r"(r2), "=r"(r3) : "r"(addr))

#define MMA16816(C, A, b0_, b1_) \
    asm volatile("mma.sync.aligned.m16n8k16.row.col.f32.bf16.bf16.f32 " \
                 "{%0,%1,%2,%3},{%4,%5,%6,%7},{%8,%9},{%0,%1,%2,%3};" \
                 : "+f"((C)[0]), "+f"((C)[1]), "+f"((C)[2]), "+f"((C)[3]) \
                 : "r"((A)[0]), "r"((A)[1]), "r"((A)[2]), "r"((A)[3]), \
                   "r"(b0_), "r"(b1_))

// truncation split: v = hi(bf16 trunc) + lo(bf16 rn); packs a pair (v0 low).
__device__ __forceinline__ void split_pair(float v0, float v1,
                                           uint32_t& hi_pk, uint32_t& lo_pk) {
    uint32_t u0 = __float_as_uint(v0), u1 = __float_as_uint(v1);
    hi_pk = __byte_perm(u0, u1, 0x7632);          // {v1.hi16 : v0.hi16}
    float l0 = v0 - __uint_as_float(u0 & 0xFFFF0000u);
    float l1 = v1 - __uint_as_float(u1 & 0xFFFF0000u);
    asm("cvt.rn.bf16x2.f32 %0, %1, %2;" : "=r"(lo_pk) : "f"(l1), "f"(l0));
}

__device__ __forceinline__ float relu(float v) { return fmaxf(v, 0.0f); }

// ---------------------------------------------------------------------------
// Prep kernel: split Wh fp32 -> (hi,lo) bf16 into the swizzled image.
// ---------------------------------------------------------------------------
__global__ void prep_weights_kernel(const float* __restrict__ Wh) {
    int idx = blockIdx.x * blockDim.x + threadIdx.x;
    if (idx >= NHID * 128 * 128) return;
    int l = idx >> 14;
    int n = (idx >> 7) & 127;     // out feature
    int k = idx & 127;            // in feature
    float v = Wh[idx];
    uint32_t u = __float_as_uint(v);
    unsigned short hi = (unsigned short)(u >> 16);
    float lof = v - __uint_as_float(u & 0xFFFF0000u);
    __nv_bfloat16 lo = __float2bfloat16(lof);
    uint32_t chunk = (uint32_t)k >> 3;
    uint32_t off = (uint32_t)n * 256 + ((chunk ^ ((uint32_t)n & 7)) << 4)
                 + ((uint32_t)k & 7) * 2;
    *(unsigned short*)&g_wimg[l][off]         = hi;
    *(unsigned short*)&g_wimg[l][off + 32768] = *(unsigned short*)&lo;
}

// issue cp.async prefetch of one 64KB layer image into the single buffer
__device__ __forceinline__ void prefetch_layer(uint32_t sb, int layer, int tid) {
    const char* src = (const char*)&g_wimg[layer][0];
    uint32_t dst = sb + SM_WBUF;
    #pragma unroll
    for (int i = 0; i < 32; i++)
        CP_ASYNC16(dst + (uint32_t)(tid + i * THREADS) * 16,
                   src + (size_t)(tid + i * THREADS) * 16);
    CP_COMMIT();
}

// ---------------------------------------------------------------------------
// Main kernel: 64 rows per CTA, 4 warps, 2 CTAs co-resident per SM.
// ---------------------------------------------------------------------------
__global__ void __launch_bounds__(THREADS, 2)
mlp_kernel(const float* __restrict__ x,
           const float* __restrict__ W0,
           const float* __restrict__ b0,
           const float* __restrict__ bh,
           const float* __restrict__ Wout,
           const float* __restrict__ bout,
           float* __restrict__ out) {
    extern __shared__ char smem[];
    const uint32_t sb = smem_u32(smem);
    const int tid  = threadIdx.x;
    const int wid  = tid >> 5;
    const int lane = tid & 31;
    const int q    = lane & 3;          // quad index (col pair selector)

    // ---- layer-0 weights in flight before any compute ----
    prefetch_layer(sb, 0, tid);

    // ---- stage small params ----
    {
        float* bias_s = (float*)(smem + SM_BIAS);
        for (int i = tid; i < NHID * 128; i += THREADS) bias_s[i] = bh[i];
        if (tid < 128) {
            float* w0s = (float*)(smem + SM_W0);
            w0s[tid * 3 + 0] = W0[tid * 3 + 0];
            w0s[tid * 3 + 1] = W0[tid * 3 + 1];
            w0s[tid * 3 + 2] = W0[tid * 3 + 2];
            ((float*)(smem + SM_B0))[tid] = b0[tid];
        }
        float* wos = (float*)(smem + SM_WOUT);
        for (int i = tid; i < 384; i += THREADS) wos[i] = Wout[i];
        if (tid < 3) ((float*)(smem + SM_BOUT))[tid] = bout[tid];
    }
    __syncthreads();

    // global rows owned by this thread (2 per thread, m16 tile per warp)
    const int rbase = blockIdx.x * ROWS_PER_CTA + wid * 16 + (lane >> 2);
    const int g0 = rbase;        // row t/4
    const int g1 = rbase + 8;    // row t/4 + 8

    // ---- layer 0: [3 -> 128] in fp32 FFMA, produce A fragments ----
    uint32_t Ahi[8][4], Alo[8][4];
    {
        const float x00 = x[g0 * 3 + 0], x01 = x[g0 * 3 + 1], x02 = x[g0 * 3 + 2];
        const float x10 = x[g1 * 3 + 0], x11 = x[g1 * 3 + 1], x12 = x[g1 * 3 + 2];
        const float* w0s = (const float*)(smem + SM_W0);
        const float* b0s = (const float*)(smem + SM_B0);
        #pragma unroll
        for (int s = 0; s < 8; s++) {
            const int c0 = 16 * s + 2 * q;
            #pragma unroll
            for (int h = 0; h < 2; h++) {
                const int ca = c0 + 8 * h;
                const float wa0 = w0s[ca * 3 + 0], wa1 = w0s[ca * 3 + 1], wa2 = w0s[ca * 3 + 2];
                const float wb0 = w0s[(ca + 1) * 3 + 0], wb1 = w0s[(ca + 1) * 3 + 1], wb2 = w0s[(ca + 1) * 3 + 2];
                const float ba = b0s[ca], bb = b0s[ca + 1];
                float v00 = relu(fmaf(x00, wa0, fmaf(x01, wa1, fmaf(x02, wa2, ba))));
                float v01 = relu(fmaf(x00, wb0, fmaf(x01, wb1, fmaf(x02, wb2, bb))));
                float v10 = relu(fmaf(x10, wa0, fmaf(x11, wa1, fmaf(x12, wa2, ba))));
                float v11 = relu(fmaf(x10, wb0, fmaf(x11, wb1, fmaf(x12, wb2, bb))));
                split_pair(v00, v01, Ahi[s][2 * h + 0], Alo[s][2 * h + 0]);
                split_pair(v10, v11, Ahi[s][2 * h + 1], Alo[s][2 * h + 1]);
            }
        }
    }

    // per-thread ldmatrix address pieces
    const uint32_t nloc = (uint32_t)((lane & 7) + ((lane >> 4) & 1) * 8); // 0..15
    const uint32_t jbit = (uint32_t)((lane >> 3) & 1);                   // chunk +1
    uint32_t swz[8];
    #pragma unroll
    for (int s = 0; s < 8; s++)
        swz[s] = nloc * 256 + ((((uint32_t)(2 * s) + jbit) ^ (nloc & 7)) << 4);

    const float* bias_s = (const float*)(smem + SM_BIAS);
    const float* wout_s = (const float*)(smem + SM_WOUT);
    const float* bout_s = (const float*)(smem + SM_BOUT);

    // wait for layer-0 weights
    CP_WAIT(0);
    __syncthreads();

    // ---- 7 hidden layers ----
    #pragma unroll 1
    for (int l = 0; l < NHID; l++) {
        const uint32_t wb = sb + SM_WBUF;

        float C[16][4];
        #pragma unroll
        for (int g = 0; g < 16; g++)
            { C[g][0] = 0.f; C[g][1] = 0.f; C[g][2] = 0.f; C[g][3] = 0.f; }

        #pragma unroll
        for (int s = 0; s < 8; s++) {
            const uint32_t base = wb + swz[s];
            #pragma unroll
            for (int pp = 0; pp < 4; pp++) {     // p-pairs: 4 independent C regs
                const uint32_t a0 = base + (uint32_t)(2 * pp) * 4096;
                const uint32_t a1 = a0 + 4096;
                uint32_t h0, h1, h2, h3, h4, h5, h6, h7;
                uint32_t w0_, w1_, w2_, w3_, w4_, w5_, w6_, w7_;
                LDSM4(h0, h1, h2, h3, a0);             // Whi p=2pp
                LDSM4(h4, h5, h6, h7, a1);             // Whi p=2pp+1
                LDSM4(w0_, w1_, w2_, w3_, a0 + 32768); // Wlo p=2pp
                LDSM4(w4_, w5_, w6_, w7_, a1 + 32768); // Wlo p=2pp+1
                float* C0 = C[4 * pp + 0];
                float* C1 = C[4 * pp + 1];
                float* C2 = C[4 * pp + 2];
                float* C3 = C[4 * pp + 3];
                MMA16816(C0, Ahi[s], h0, h1);
                MMA16816(C1, Ahi[s], h2, h3);
                MMA16816(C2, Ahi[s], h4, h5);
                MMA16816(C3, Ahi[s], h6, h7);
                MMA16816(C0, Alo[s], h0, h1);
                MMA16816(C1, Alo[s], h2, h3);
                MMA16816(C2, Alo[s], h4, h5);
                MMA16816(C3, Alo[s], h6, h7);
                MMA16816(C0, Ahi[s], w0_, w1_);
                MMA16816(C1, Ahi[s], w2_, w3_);
                MMA16816(C2, Ahi[s], w4_, w5_);
                MMA16816(C3, Ahi[s], w6_, w7_);
            }
        }

        // all warps finished reading the weight buffer -> refill for l+1,
        // hidden behind this CTA's epilogue and the other CTA's MMAs.
        __syncthreads();
        if (l + 1 < NHID) prefetch_layer(sb, l + 1, tid);

        const float* bl = bias_s + l * 128;

        if (l < NHID - 1) {
            // bias + relu + split -> next layer A fragments
            #pragma unroll
            for (int s = 0; s < 8; s++) {
                const float2 bb0 = *(const float2*)&bl[16 * s + 2 * q];
                const float2 bb1 = *(const float2*)&bl[16 * s + 8 + 2 * q];
                float v00 = relu(C[2 * s][0] + bb0.x);
                float v01 = relu(C[2 * s][1] + bb0.y);
                float v10 = relu(C[2 * s][2] + bb0.x);
                float v11 = relu(C[2 * s][3] + bb0.y);
                split_pair(v00, v01, Ahi[s][0], Alo[s][0]);
                split_pair(v10, v11, Ahi[s][1], Alo[s][1]);
                float w00 = relu(C[2 * s + 1][0] + bb1.x);
                float w01 = relu(C[2 * s + 1][1] + bb1.y);
                float w10 = relu(C[2 * s + 1][2] + bb1.x);
                float w11 = relu(C[2 * s + 1][3] + bb1.y);
                split_pair(w00, w01, Ahi[s][2], Alo[s][2]);
                split_pair(w10, w11, Ahi[s][3], Alo[s][3]);
            }
            CP_WAIT(0);
            __syncthreads();   // buf[l+1] visible to all warps
        } else {
            // final: bias + relu, fused [128 -> 3] projection + bout
            float o00 = 0.f, o01 = 0.f, o02 = 0.f;   // row g0
            float o10 = 0.f, o11 = 0.f, o12 = 0.f;   // row g1
            #pragma unroll
            for (int g = 0; g < 16; g++) {
                const int c = 8 * g + 2 * q;
                const float2 bb = *(const float2*)&bl[c];
                float v00 = relu(C[g][0] + bb.x);
                float v01 = relu(C[g][1] + bb.y);
                float v10 = relu(C[g][2] + bb.x);
                float v11 = relu(C[g][3] + bb.y);
                const float2 wj0 = *(const float2*)&wout_s[0 * 128 + c];
                const float2 wj1 = *(const float2*)&wout_s[1 * 128 + c];
                const float2 wj2 = *(const float2*)&wout_s[2 * 128 + c];
                o00 = fmaf(v00, wj0.x, fmaf(v01, wj0.y, o00));
                o01 = fmaf(v00, wj1.x, fmaf(v01, wj1.y, o01));
                o02 = fmaf(v00, wj2.x, fmaf(v01, wj2.y, o02));
                o10 = fmaf(v10, wj0.x, fmaf(v11, wj0.y, o10));
                o11 = fmaf(v10, wj1.x, fmaf(v11, wj1.y, o11));
                o12 = fmaf(v10, wj2.x, fmaf(v11, wj2.y, o12));
            }
            #pragma unroll
            for (int d = 1; d <= 2; d <<= 1) {
                o00 += __shfl_xor_sync(0xFFFFFFFF, o00, d);
                o01 += __shfl_xor_sync(0xFFFFFFFF, o01, d);
                o02 += __shfl_xor_sync(0xFFFFFFFF, o02, d);
                o10 += __shfl_xor_sync(0xFFFFFFFF, o10, d);
                o11 += __shfl_xor_sync(0xFFFFFFFF, o11, d);
                o12 += __shfl_xor_sync(0xFFFFFFFF, o12, d);
            }
            if (q == 0) {
                out[g0 * 3 + 0] = o00 + bout_s[0];
                out[g0 * 3 + 1] = o01 + bout_s[1];
                out[g0 * 3 + 2] = o02 + bout_s[2];
                out[g1 * 3 + 0] = o10 + bout_s[0];
                out[g1 * 3 + 1] = o11 + bout_s[1];
                out[g1 * 3 + 2] = o12 + bout_s[2];
            }
        }
    }
}

// ---------------------------------------------------------------------------
// kernel_launch
// ---------------------------------------------------------------------------
extern "C" void kernel_launch(void* const* d_in, const int* in_sizes, int n_in,
                              void* d_out, int out_size) {
    const float* x    = (const float*)d_in[0];   // [262144,3]
    const float* W0   = (const float*)d_in[1];   // [128,3]
    const float* b0   = (const float*)d_in[2];   // [128]
    const float* Wh   = (const float*)d_in[3];   // [7,128,128]
    const float* bh   = (const float*)d_in[4];   // [7,128]
    const float* Wout = (const float*)d_in[5];   // [3,128]
    const float* bout = (const float*)d_in[6];   // [3]
    float* out = (float*)d_out;                  // [262144,3]

    static bool attr_set = false;
    if (!attr_set) {
        cudaFuncSetAttribute(mlp_kernel,
                             cudaFuncAttributeMaxDynamicSharedMemorySize, SMEM_SZ);
        attr_set = true;
    }

    prep_weights_kernel<<<(NHID * 128 * 128 + 255) / 256, 256>>>(Wh);
    mlp_kernel<<<NTILES, THREADS, SMEM_SZ>>>(x, W0, b0, bh, Wout, bout, out);
}

// round 6
// speedup vs baseline: 1.4890x; 1.2916x over previous
#include <cuda_runtime.h>
#include <cuda_fp16.h>
#include <cstdint>

// ============================================================================
// NSFPRawMLP: x[262144,3] -> 128 -> (7x 128x128 + ReLU) -> 3
// R6: fp16 2-product split-GEMM:  C = Ahi*W16 + Alo*W16
//   - activations split hi/lo fp16 (captured to ~2^-22)
//   - weights single fp16 image (rounding 2^-12, RMS ~1e-4/layer -> ~3e-4 total)
// 64 MMAs/warp/layer (was 96), 32KB weights/layer (was 64KB),
// double-buffered weights (2x32KB, still 2 CTAs/SM), 128 thr / 64 rows per CTA.
// ============================================================================

#define NROWS   262144
#define NHID    7
#define ROWS_PER_CTA 64
#define NTILES  (NROWS / ROWS_PER_CTA)   // 4096 CTAs
#define THREADS 128                      // 4 warps, 16 rows/warp

// Weight images: [layer][32768 B] fp16.
// byte = n*256 + ((chunk ^ (n&7))<<4) + (k&7)*2, chunk = k>>3  (XOR swizzle)
static __device__ __align__(128) unsigned char g_wimg[NHID][32768];

// ---------------------------------------------------------------------------
// SMEM layout (dynamic): TWO weight buffers + small params (~72.7KB -> 2 CTA/SM)
// ---------------------------------------------------------------------------
#define SM_WBUF    0                     // 2 x 32768 = 65536
#define SM_BIAS    65536                 // 7*128 f32 = 3584
#define SM_W0      (SM_BIAS + 3584)      // 128*3 f32 = 1536
#define SM_B0      (SM_W0 + 1536)        // 128 f32  = 512
#define SM_WOUT    (SM_B0 + 512)         // 3*128 f32 = 1536
#define SM_BOUT    (SM_WOUT + 1536)      // 16
#define SMEM_SZ    (SM_BOUT + 16)        // 72,720 B

// ---------------------------------------------------------------------------
// PTX helpers (base-target, sm_80+)
// ---------------------------------------------------------------------------
__device__ __forceinline__ uint32_t smem_u32(const void* p) {
    uint32_t a;
    asm("{ .reg .u64 t; cvta.to.shared.u64 t, %1; cvt.u32.u64 %0, t; }"
        : "=r"(a) : "l"(p));
    return a;
}

#define CP_ASYNC16(dst_u32, src_ptr) \
    asm volatile("cp.async.cg.shared.global [%0], [%1], 16;" \
                 :: "r"(dst_u32), "l"(src_ptr) : "memory")
#define CP_COMMIT() asm volatile("cp.async.commit_group;" ::: "memory")
#define CP_WAIT(n)  asm volatile("cp.async.wait_group %0;" :: "n"(n) : "memory")

#define LDSM4(r0, r1, r2, r3, addr) \
    asm volatile("ldmatrix.sync.aligned.m8n8.x4.shared.b16 {%0,%1,%2,%3}, [%4];" \
                 : "=r"(r0), "=r"(r1), "=r"(r2), "=r"(r3) : "r"(addr))

#define MMA16816(C, A, b0_, b1_) \
    asm volatile("mma.sync.aligned.m16n8k16.row.col.f32.f16.f16.f32 " \
                 "{%0,%1,%2,%3},{%4,%5,%6,%7},{%8,%9},{%0,%1,%2,%3};" \
                 : "+f"((C)[0]), "+f"((C)[1]), "+f"((C)[2]), "+f"((C)[3]) \
                 : "r"((A)[0]), "r"((A)[1]), "r"((A)[2]), "r"((A)[3]), \
                   "r"(b0_), "r"(b1_))

// fp16 truncation-style split: v = hi(f16 rn) + lo(f16 rn of residual)
__device__ __forceinline__ void split_pair(float v0, float v1,
                                           uint32_t& hi_pk, uint32_t& lo_pk) {
    asm("cvt.rn.f16x2.f32 %0, %1, %2;" : "=r"(hi_pk) : "f"(v1), "f"(v0));
    __half2 h = *reinterpret_cast<__half2*>(&hi_pk);
    float l0 = v0 - __low2float(h);
    float l1 = v1 - __high2float(h);
    asm("cvt.rn.f16x2.f32 %0, %1, %2;" : "=r"(lo_pk) : "f"(l1), "f"(l0));
}

__device__ __forceinline__ float relu(float v) { return fmaxf(v, 0.0f); }

// ---------------------------------------------------------------------------
// Prep kernel: Wh fp32 -> fp16 swizzled image.
// ---------------------------------------------------------------------------
__global__ void prep_weights_kernel(const float* __restrict__ Wh) {
    int idx = blockIdx.x * blockDim.x + threadIdx.x;
    if (idx >= NHID * 128 * 128) return;
    int l = idx >> 14;
    int n = (idx >> 7) & 127;     // out feature
    int k = idx & 127;            // in feature
    __half w = __float2half_rn(Wh[idx]);
    uint32_t chunk = (uint32_t)k >> 3;
    uint32_t off = (uint32_t)n * 256 + ((chunk ^ ((uint32_t)n & 7)) << 4)
                 + ((uint32_t)k & 7) * 2;
    *(__half*)&g_wimg[l][off] = w;
}

// issue cp.async prefetch of one 32KB layer image into buf[layer&1]
__device__ __forceinline__ void prefetch_layer(uint32_t sb, int layer, int tid) {
    const char* src = (const char*)&g_wimg[layer][0];
    uint32_t dst = sb + SM_WBUF + (uint32_t)(layer & 1) * 32768;
    #pragma unroll
    for (int i = 0; i < 16; i++)
        CP_ASYNC16(dst + (uint32_t)(tid + i * THREADS) * 16,
                   src + (size_t)(tid + i * THREADS) * 16);
    CP_COMMIT();
}

// ---------------------------------------------------------------------------
// Main kernel: 64 rows per CTA, 4 warps, 2 CTAs co-resident per SM.
// ---------------------------------------------------------------------------
__global__ void __launch_bounds__(THREADS, 2)
mlp_kernel(const float* __restrict__ x,
           const float* __restrict__ W0,
           const float* __restrict__ b0,
           const float* __restrict__ bh,
           const float* __restrict__ Wout,
           const float* __restrict__ bout,
           float* __restrict__ out) {
    extern __shared__ char smem[];
    const uint32_t sb = smem_u32(smem);
    const int tid  = threadIdx.x;
    const int wid  = tid >> 5;
    const int lane = tid & 31;
    const int q    = lane & 3;          // quad index (col pair selector)

    // ---- layer-0 weights in flight before any compute ----
    prefetch_layer(sb, 0, tid);

    // ---- stage small params ----
    {
        float* bias_s = (float*)(smem + SM_BIAS);
        for (int i = tid; i < NHID * 128; i += THREADS) bias_s[i] = bh[i];
        if (tid < 128) {
            float* w0s = (float*)(smem + SM_W0);
            w0s[tid * 3 + 0] = W0[tid * 3 + 0];
            w0s[tid * 3 + 1] = W0[tid * 3 + 1];
            w0s[tid * 3 + 2] = W0[tid * 3 + 2];
            ((float*)(smem + SM_B0))[tid] = b0[tid];
        }
        float* wos = (float*)(smem + SM_WOUT);
        for (int i = tid; i < 384; i += THREADS) wos[i] = Wout[i];
        if (tid < 3) ((float*)(smem + SM_BOUT))[tid] = bout[tid];
    }
    __syncthreads();

    // global rows owned by this thread (2 per thread, m16 tile per warp)
    const int rbase = blockIdx.x * ROWS_PER_CTA + wid * 16 + (lane >> 2);
    const int g0 = rbase;        // row t/4
    const int g1 = rbase + 8;    // row t/4 + 8

    // ---- layer 0: [3 -> 128] in fp32 FFMA, produce A fragments ----
    uint32_t Ahi[8][4], Alo[8][4];
    {
        const float x00 = x[g0 * 3 + 0], x01 = x[g0 * 3 + 1], x02 = x[g0 * 3 + 2];
        const float x10 = x[g1 * 3 + 0], x11 = x[g1 * 3 + 1], x12 = x[g1 * 3 + 2];
        const float* w0s = (const float*)(smem + SM_W0);
        const float* b0s = (const float*)(smem + SM_B0);
        #pragma unroll
        for (int s = 0; s < 8; s++) {
            const int c0 = 16 * s + 2 * q;
            #pragma unroll
            for (int h = 0; h < 2; h++) {
                const int ca = c0 + 8 * h;
                const float wa0 = w0s[ca * 3 + 0], wa1 = w0s[ca * 3 + 1], wa2 = w0s[ca * 3 + 2];
                const float wb0 = w0s[(ca + 1) * 3 + 0], wb1 = w0s[(ca + 1) * 3 + 1], wb2 = w0s[(ca + 1) * 3 + 2];
                const float ba = b0s[ca], bb = b0s[ca + 1];
                float v00 = relu(fmaf(x00, wa0, fmaf(x01, wa1, fmaf(x02, wa2, ba))));
                float v01 = relu(fmaf(x00, wb0, fmaf(x01, wb1, fmaf(x02, wb2, bb))));
                float v10 = relu(fmaf(x10, wa0, fmaf(x11, wa1, fmaf(x12, wa2, ba))));
                float v11 = relu(fmaf(x10, wb0, fmaf(x11, wb1, fmaf(x12, wb2, bb))));
                split_pair(v00, v01, Ahi[s][2 * h + 0], Alo[s][2 * h + 0]);
                split_pair(v10, v11, Ahi[s][2 * h + 1], Alo[s][2 * h + 1]);
            }
        }
    }

    // per-thread ldmatrix address pieces
    const uint32_t nloc = (uint32_t)((lane & 7) + ((lane >> 4) & 1) * 8); // 0..15
    const uint32_t jbit = (uint32_t)((lane >> 3) & 1);                   // chunk +1
    uint32_t swz[8];
    #pragma unroll
    for (int s = 0; s < 8; s++)
        swz[s] = nloc * 256 + ((((uint32_t)(2 * s) + jbit) ^ (nloc & 7)) << 4);

    const float* bias_s = (const float*)(smem + SM_BIAS);
    const float* wout_s = (const float*)(smem + SM_WOUT);
    const float* bout_s = (const float*)(smem + SM_BOUT);

    // wait for layer-0 weights
    CP_WAIT(0);
    __syncthreads();

    // ---- 7 hidden layers, double-buffered weights ----
    #pragma unroll 1
    for (int l = 0; l < NHID; l++) {
        // buf[(l+1)&1] is free (layer l-1 MMAs finished before last barrier):
        // start refilling it now; the load overlaps this whole layer.
        if (l + 1 < NHID) prefetch_layer(sb, l + 1, tid);

        const uint32_t wb = sb + SM_WBUF + (uint32_t)(l & 1) * 32768;

        float C[16][4];
        #pragma unroll
        for (int g = 0; g < 16; g++)
            { C[g][0] = 0.f; C[g][1] = 0.f; C[g][2] = 0.f; C[g][3] = 0.f; }

        #pragma unroll
        for (int s = 0; s < 8; s++) {
            const uint32_t base = wb + swz[s];
            #pragma unroll
            for (int pp = 0; pp < 4; pp++) {     // p-pairs: 4 independent C regs
                const uint32_t a0 = base + (uint32_t)(2 * pp) * 4096;
                const uint32_t a1 = a0 + 4096;
                uint32_t h0, h1, h2, h3, h4, h5, h6, h7;
                LDSM4(h0, h1, h2, h3, a0);             // W16 p=2pp
                LDSM4(h4, h5, h6, h7, a1);             // W16 p=2pp+1
                float* C0 = C[4 * pp + 0];
                float* C1 = C[4 * pp + 1];
                float* C2 = C[4 * pp + 2];
                float* C3 = C[4 * pp + 3];
                MMA16816(C0, Ahi[s], h0, h1);
                MMA16816(C1, Ahi[s], h2, h3);
                MMA16816(C2, Ahi[s], h4, h5);
                MMA16816(C3, Ahi[s], h6, h7);
                MMA16816(C0, Alo[s], h0, h1);
                MMA16816(C1, Alo[s], h2, h3);
                MMA16816(C2, Alo[s], h4, h5);
                MMA16816(C3, Alo[s], h6, h7);
            }
        }

        const float* bl = bias_s + l * 128;

        if (l < NHID - 1) {
            // bias + relu + split -> next layer A fragments
            #pragma unroll
            for (int s = 0; s < 8; s++) {
                const float2 bb0 = *(const float2*)&bl[16 * s + 2 * q];
                const float2 bb1 = *(const float2*)&bl[16 * s + 8 + 2 * q];
                float v00 = relu(C[2 * s][0] + bb0.x);
                float v01 = relu(C[2 * s][1] + bb0.y);
                float v10 = relu(C[2 * s][2] + bb0.x);
                float v11 = relu(C[2 * s][3] + bb0.y);
                split_pair(v00, v01, Ahi[s][0], Alo[s][0]);
                split_pair(v10, v11, Ahi[s][1], Alo[s][1]);
                float w00 = relu(C[2 * s + 1][0] + bb1.x);
                float w01 = relu(C[2 * s + 1][1] + bb1.y);
                float w10 = relu(C[2 * s + 1][2] + bb1.x);
                float w11 = relu(C[2 * s + 1][3] + bb1.y);
                split_pair(w00, w01, Ahi[s][2], Alo[s][2]);
                split_pair(w10, w11, Ahi[s][3], Alo[s][3]);
            }
            CP_WAIT(0);        // next layer's weights landed (overlapped all of this layer)
            __syncthreads();   // visibility + all warps done reading buf[l&1]
        } else {
            // final: bias + relu, fused [128 -> 3] projection + bout
            float o00 = 0.f, o01 = 0.f, o02 = 0.f;   // row g0
            float o10 = 0.f, o11 = 0.f, o12 = 0.f;   // row g1
            #pragma unroll
            for (int g = 0; g < 16; g++) {
                const int c = 8 * g + 2 * q;
                const float2 bb = *(const float2*)&bl[c];
                float v00 = relu(C[g][0] + bb.x);
                float v01 = relu(C[g][1] + bb.y);
                float v10 = relu(C[g][2] + bb.x);
                float v11 = relu(C[g][3] + bb.y);
                const float2 wj0 = *(const float2*)&wout_s[0 * 128 + c];
                const float2 wj1 = *(const float2*)&wout_s[1 * 128 + c];
                const float2 wj2 = *(const float2*)&wout_s[2 * 128 + c];
                o00 = fmaf(v00, wj0.x, fmaf(v01, wj0.y, o00));
                o01 = fmaf(v00, wj1.x, fmaf(v01, wj1.y, o01));
                o02 = fmaf(v00, wj2.x, fmaf(v01, wj2.y, o02));
                o10 = fmaf(v10, wj0.x, fmaf(v11, wj0.y, o10));
                o11 = fmaf(v10, wj1.x, fmaf(v11, wj1.y, o11));
                o12 = fmaf(v10, wj2.x, fmaf(v11, wj2.y, o12));
            }
            #pragma unroll
            for (int d = 1; d <= 2; d <<= 1) {
                o00 += __shfl_xor_sync(0xFFFFFFFF, o00, d);
                o01 += __shfl_xor_sync(0xFFFFFFFF, o01, d);
                o02 += __shfl_xor_sync(0xFFFFFFFF, o02, d);
                o10 += __shfl_xor_sync(0xFFFFFFFF, o10, d);
                o11 += __shfl_xor_sync(0xFFFFFFFF, o11, d);
                o12 += __shfl_xor_sync(0xFFFFFFFF, o12, d);
            }
            if (q == 0) {
                out[g0 * 3 + 0] = o00 + bout_s[0];
                out[g0 * 3 + 1] = o01 + bout_s[1];
                out[g0 * 3 + 2] = o02 + bout_s[2];
                out[g1 * 3 + 0] = o10 + bout_s[0];
                out[g1 * 3 + 1] = o11 + bout_s[1];
                out[g1 * 3 + 2] = o12 + bout_s[2];
            }
        }
    }
}

// ---------------------------------------------------------------------------
// kernel_launch
// ---------------------------------------------------------------------------
extern "C" void kernel_launch(void* const* d_in, const int* in_sizes, int n_in,
                              void* d_out, int out_size) {
    const float* x    = (const float*)d_in[0];   // [262144,3]
    const float* W0   = (const float*)d_in[1];   // [128,3]
    const float* b0   = (const float*)d_in[2];   // [128]
    const float* Wh   = (const float*)d_in[3];   // [7,128,128]
    const float* bh   = (const float*)d_in[4];   // [7,128]
    const float* Wout = (const float*)d_in[5];   // [3,128]
    const float* bout = (const float*)d_in[6];   // [3]
    float* out = (float*)d_out;                  // [262144,3]

    static bool attr_set = false;
    if (!attr_set) {
        cudaFuncSetAttribute(mlp_kernel,
                             cudaFuncAttributeMaxDynamicSharedMemorySize, SMEM_SZ);
        attr_set = true;
    }

    prep_weights_kernel<<<(NHID * 128 * 128 + 255) / 256, 256>>>(Wh);
    mlp_kernel<<<NTILES, THREADS, SMEM_SZ>>>(x, W0, b0, bh, Wout, bout, out);
}

// round 7
// speedup vs baseline: 2.7388x; 1.8393x over previous
#include <cuda_runtime.h>
#include <cuda_fp16.h>
#include <cstdint>

// ============================================================================
// NSFPRawMLP: x[262144,3] -> 128 -> (7x 128x128 + ReLU) -> 3
// R7: single-product fp16 GEMM:  C = f16(A) * f16(W), fp32 accumulate.
//   (error margin from R6 measurement funds dropping the Alo product)
// 64 MMAs/warp/layer (was 128), cheap epilogue (1 cvt, no residual),
// regs ~145 -> 3 CTAs/SM (launch_bounds(128,3)), double-buffered weights.
// ============================================================================

#define NROWS   262144
#define NHID    7
#define ROWS_PER_CTA 64
#define NTILES  (NROWS / ROWS_PER_CTA)   // 4096 CTAs
#define THREADS 128                      // 4 warps, 16 rows/warp

// Weight images: [layer][32768 B] fp16.
// byte = n*256 + ((chunk ^ (n&7))<<4) + (k&7)*2, chunk = k>>3  (XOR swizzle)
static __device__ __align__(128) unsigned char g_wimg[NHID][32768];

// ---------------------------------------------------------------------------
// SMEM layout (dynamic): TWO weight buffers + small params (~72.7KB -> 3 CTA/SM)
// ---------------------------------------------------------------------------
#define SM_WBUF    0                     // 2 x 32768 = 65536
#define SM_BIAS    65536                 // 7*128 f32 = 3584
#define SM_W0      (SM_BIAS + 3584)      // 128*3 f32 = 1536
#define SM_B0      (SM_W0 + 1536)        // 128 f32  = 512
#define SM_WOUT    (SM_B0 + 512)         // 3*128 f32 = 1536
#define SM_BOUT    (SM_WOUT + 1536)      // 16
#define SMEM_SZ    (SM_BOUT + 16)        // 72,720 B

// ---------------------------------------------------------------------------
// PTX helpers (base-target, sm_80+)
// ---------------------------------------------------------------------------
__device__ __forceinline__ uint32_t smem_u32(const void* p) {
    uint32_t a;
    asm("{ .reg .u64 t; cvta.to.shared.u64 t, %1; cvt.u32.u64 %0, t; }"
        : "=r"(a) : "l"(p));
    return a;
}

#define CP_ASYNC16(dst_u32, src_ptr) \
    asm volatile("cp.async.cg.shared.global [%0], [%1], 16;" \
                 :: "r"(dst_u32), "l"(src_ptr) : "memory")
#define CP_COMMIT() asm volatile("cp.async.commit_group;" ::: "memory")
#define CP_WAIT(n)  asm volatile("cp.async.wait_group %0;" :: "n"(n) : "memory")

#define LDSM4(r0, r1, r2, r3, addr) \
    asm volatile("ldmatrix.sync.aligned.m8n8.x4.shared.b16 {%0,%1,%2,%3}, [%4];" \
                 : "=r"(r0), "=r"(r1), "=r"(r2), "=r"(r3) : "r"(addr))

#define MMA16816(C, A, b0_, b1_) \
    asm volatile("mma.sync.aligned.m16n8k16.row.col.f32.f16.f16.f32 " \
                 "{%0,%1,%2,%3},{%4,%5,%6,%7},{%8,%9},{%0,%1,%2,%3};" \
                 : "+f"((C)[0]), "+f"((C)[1]), "+f"((C)[2]), "+f"((C)[3]) \
                 : "r"((A)[0]), "r"((A)[1]), "r"((A)[2]), "r"((A)[3]), \
                   "r"(b0_), "r"(b1_))

// pack two fp32 -> fp16x2 (round-to-nearest)
__device__ __forceinline__ uint32_t pack_f16(float v0, float v1) {
    uint32_t r;
    asm("cvt.rn.f16x2.f32 %0, %1, %2;" : "=r"(r) : "f"(v1), "f"(v0));
    return r;
}

__device__ __forceinline__ float relu(float v) { return fmaxf(v, 0.0f); }

// ---------------------------------------------------------------------------
// Prep kernel: Wh fp32 -> fp16 swizzled image.
// ---------------------------------------------------------------------------
__global__ void prep_weights_kernel(const float* __restrict__ Wh) {
    int idx = blockIdx.x * blockDim.x + threadIdx.x;
    if (idx >= NHID * 128 * 128) return;
    int l = idx >> 14;
    int n = (idx >> 7) & 127;     // out feature
    int k = idx & 127;            // in feature
    __half w = __float2half_rn(Wh[idx]);
    uint32_t chunk = (uint32_t)k >> 3;
    uint32_t off = (uint32_t)n * 256 + ((chunk ^ ((uint32_t)n & 7)) << 4)
                 + ((uint32_t)k & 7) * 2;
    *(__half*)&g_wimg[l][off] = w;
}

// issue cp.async prefetch of one 32KB layer image into buf[layer&1]
__device__ __forceinline__ void prefetch_layer(uint32_t sb, int layer, int tid) {
    const char* src = (const char*)&g_wimg[layer][0];
    uint32_t dst = sb + SM_WBUF + (uint32_t)(layer & 1) * 32768;
    #pragma unroll
    for (int i = 0; i < 16; i++)
        CP_ASYNC16(dst + (uint32_t)(tid + i * THREADS) * 16,
                   src + (size_t)(tid + i * THREADS) * 16);
    CP_COMMIT();
}

// ---------------------------------------------------------------------------
// Main kernel: 64 rows per CTA, 4 warps, 3 CTAs co-resident per SM.
// ---------------------------------------------------------------------------
__global__ void __launch_bounds__(THREADS, 3)
mlp_kernel(const float* __restrict__ x,
           const float* __restrict__ W0,
           const float* __restrict__ b0,
           const float* __restrict__ bh,
           const float* __restrict__ Wout,
           const float* __restrict__ bout,
           float* __restrict__ out) {
    extern __shared__ char smem[];
    const uint32_t sb = smem_u32(smem);
    const int tid  = threadIdx.x;
    const int wid  = tid >> 5;
    const int lane = tid & 31;
    const int q    = lane & 3;          // quad index (col pair selector)

    // ---- layer-0 weights in flight before any compute ----
    prefetch_layer(sb, 0, tid);

    // ---- stage small params ----
    {
        float* bias_s = (float*)(smem + SM_BIAS);
        for (int i = tid; i < NHID * 128; i += THREADS) bias_s[i] = bh[i];
        if (tid < 128) {
            float* w0s = (float*)(smem + SM_W0);
            w0s[tid * 3 + 0] = W0[tid * 3 + 0];
            w0s[tid * 3 + 1] = W0[tid * 3 + 1];
            w0s[tid * 3 + 2] = W0[tid * 3 + 2];
            ((float*)(smem + SM_B0))[tid] = b0[tid];
        }
        float* wos = (float*)(smem + SM_WOUT);
        for (int i = tid; i < 384; i += THREADS) wos[i] = Wout[i];
        if (tid < 3) ((float*)(smem + SM_BOUT))[tid] = bout[tid];
    }
    __syncthreads();

    // global rows owned by this thread (2 per thread, m16 tile per warp)
    const int rbase = blockIdx.x * ROWS_PER_CTA + wid * 16 + (lane >> 2);
    const int g0 = rbase;        // row t/4
    const int g1 = rbase + 8;    // row t/4 + 8

    // ---- layer 0: [3 -> 128] in fp32 FFMA, produce fp16 A fragments ----
    uint32_t A[8][4];
    {
        const float x00 = x[g0 * 3 + 0], x01 = x[g0 * 3 + 1], x02 = x[g0 * 3 + 2];
        const float x10 = x[g1 * 3 + 0], x11 = x[g1 * 3 + 1], x12 = x[g1 * 3 + 2];
        const float* w0s = (const float*)(smem + SM_W0);
        const float* b0s = (const float*)(smem + SM_B0);
        #pragma unroll
        for (int s = 0; s < 8; s++) {
            const int c0 = 16 * s + 2 * q;
            #pragma unroll
            for (int h = 0; h < 2; h++) {
                const int ca = c0 + 8 * h;
                const float wa0 = w0s[ca * 3 + 0], wa1 = w0s[ca * 3 + 1], wa2 = w0s[ca * 3 + 2];
                const float wb0 = w0s[(ca + 1) * 3 + 0], wb1 = w0s[(ca + 1) * 3 + 1], wb2 = w0s[(ca + 1) * 3 + 2];
                const float ba = b0s[ca], bb = b0s[ca + 1];
                float v00 = relu(fmaf(x00, wa0, fmaf(x01, wa1, fmaf(x02, wa2, ba))));
                float v01 = relu(fmaf(x00, wb0, fmaf(x01, wb1, fmaf(x02, wb2, bb))));
                float v10 = relu(fmaf(x10, wa0, fmaf(x11, wa1, fmaf(x12, wa2, ba))));
                float v11 = relu(fmaf(x10, wb0, fmaf(x11, wb1, fmaf(x12, wb2, bb))));
                A[s][2 * h + 0] = pack_f16(v00, v01);
                A[s][2 * h + 1] = pack_f16(v10, v11);
            }
        }
    }

    // per-thread ldmatrix address pieces
    const uint32_t nloc = (uint32_t)((lane & 7) + ((lane >> 4) & 1) * 8); // 0..15
    const uint32_t jbit = (uint32_t)((lane >> 3) & 1);                   // chunk +1
    uint32_t swz[8];
    #pragma unroll
    for (int s = 0; s < 8; s++)
        swz[s] = nloc * 256 + ((((uint32_t)(2 * s) + jbit) ^ (nloc & 7)) << 4);

    const float* bias_s = (const float*)(smem + SM_BIAS);
    const float* wout_s = (const float*)(smem + SM_WOUT);
    const float* bout_s = (const float*)(smem + SM_BOUT);

    // wait for layer-0 weights
    CP_WAIT(0);
    __syncthreads();

    // ---- 7 hidden layers, double-buffered weights ----
    #pragma unroll 1
    for (int l = 0; l < NHID; l++) {
        // buf[(l+1)&1] is free: refill now, overlapped with this whole layer.
        if (l + 1 < NHID) prefetch_layer(sb, l + 1, tid);

        const uint32_t wb = sb + SM_WBUF + (uint32_t)(l & 1) * 32768;

        float C[16][4];
        #pragma unroll
        for (int g = 0; g < 16; g++)
            { C[g][0] = 0.f; C[g][1] = 0.f; C[g][2] = 0.f; C[g][3] = 0.f; }

        #pragma unroll
        for (int s = 0; s < 8; s++) {
            const uint32_t base = wb + swz[s];
            #pragma unroll
            for (int pp = 0; pp < 4; pp++) {     // 4 independent C tiles per pp
                const uint32_t a0 = base + (uint32_t)(2 * pp) * 4096;
                const uint32_t a1 = a0 + 4096;
                uint32_t h0, h1, h2, h3, h4, h5, h6, h7;
                LDSM4(h0, h1, h2, h3, a0);             // W16 p=2pp
                LDSM4(h4, h5, h6, h7, a1);             // W16 p=2pp+1
                MMA16816(C[4 * pp + 0], A[s], h0, h1);
                MMA16816(C[4 * pp + 1], A[s], h2, h3);
                MMA16816(C[4 * pp + 2], A[s], h4, h5);
                MMA16816(C[4 * pp + 3], A[s], h6, h7);
            }
        }

        const float* bl = bias_s + l * 128;

        if (l < NHID - 1) {
            // bias + relu + fp16 quantize -> next layer A fragments
            #pragma unroll
            for (int s = 0; s < 8; s++) {
                const float2 bb0 = *(const float2*)&bl[16 * s + 2 * q];
                const float2 bb1 = *(const float2*)&bl[16 * s + 8 + 2 * q];
                A[s][0] = pack_f16(relu(C[2 * s][0] + bb0.x), relu(C[2 * s][1] + bb0.y));
                A[s][1] = pack_f16(relu(C[2 * s][2] + bb0.x), relu(C[2 * s][3] + bb0.y));
                A[s][2] = pack_f16(relu(C[2 * s + 1][0] + bb1.x), relu(C[2 * s + 1][1] + bb1.y));
                A[s][3] = pack_f16(relu(C[2 * s + 1][2] + bb1.x), relu(C[2 * s + 1][3] + bb1.y));
            }
            CP_WAIT(0);        // next layer's weights landed
            __syncthreads();   // all warps done with buf[l&1]; buf[(l+1)&1] visible
        } else {
            // final: bias + relu, fused [128 -> 3] projection + bout
            float o00 = 0.f, o01 = 0.f, o02 = 0.f;   // row g0
            float o10 = 0.f, o11 = 0.f, o12 = 0.f;   // row g1
            #pragma unroll
            for (int g = 0; g < 16; g++) {
                const int c = 8 * g + 2 * q;
                const float2 bb = *(const float2*)&bl[c];
                float v00 = relu(C[g][0] + bb.x);
                float v01 = relu(C[g][1] + bb.y);
                float v10 = relu(C[g][2] + bb.x);
                float v11 = relu(C[g][3] + bb.y);
                const float2 wj0 = *(const float2*)&wout_s[0 * 128 + c];
                const float2 wj1 = *(const float2*)&wout_s[1 * 128 + c];
                const float2 wj2 = *(const float2*)&wout_s[2 * 128 + c];
                o00 = fmaf(v00, wj0.x, fmaf(v01, wj0.y, o00));
                o01 = fmaf(v00, wj1.x, fmaf(v01, wj1.y, o01));
                o02 = fmaf(v00, wj2.x, fmaf(v01, wj2.y, o02));
                o10 = fmaf(v10, wj0.x, fmaf(v11, wj0.y, o10));
                o11 = fmaf(v10, wj1.x, fmaf(v11, wj1.y, o11));
                o12 = fmaf(v10, wj2.x, fmaf(v11, wj2.y, o12));
            }
            #pragma unroll
            for (int d = 1; d <= 2; d <<= 1) {
                o00 += __shfl_xor_sync(0xFFFFFFFF, o00, d);
                o01 += __shfl_xor_sync(0xFFFFFFFF, o01, d);
                o02 += __shfl_xor_sync(0xFFFFFFFF, o02, d);
                o10 += __shfl_xor_sync(0xFFFFFFFF, o10, d);
                o11 += __shfl_xor_sync(0xFFFFFFFF, o11, d);
                o12 += __shfl_xor_sync(0xFFFFFFFF, o12, d);
            }
            if (q == 0) {
                out[g0 * 3 + 0] = o00 + bout_s[0];
                out[g0 * 3 + 1] = o01 + bout_s[1];
                out[g0 * 3 + 2] = o02 + bout_s[2];
                out[g1 * 3 + 0] = o10 + bout_s[0];
                out[g1 * 3 + 1] = o11 + bout_s[1];
                out[g1 * 3 + 2] = o12 + bout_s[2];
            }
        }
    }
}

// ---------------------------------------------------------------------------
// kernel_launch
// ---------------------------------------------------------------------------
extern "C" void kernel_launch(void* const* d_in, const int* in_sizes, int n_in,
                              void* d_out, int out_size) {
    const float* x    = (const float*)d_in[0];   // [262144,3]
    const float* W0   = (const float*)d_in[1];   // [128,3]
    const float* b0   = (const float*)d_in[2];   // [128]
    const float* Wh   = (const float*)d_in[3];   // [7,128,128]
    const float* bh   = (const float*)d_in[4];   // [7,128]
    const float* Wout = (const float*)d_in[5];   // [3,128]
    const float* bout = (const float*)d_in[6];   // [3]
    float* out = (float*)d_out;                  // [262144,3]

    static bool attr_set = false;
    if (!attr_set) {
        cudaFuncSetAttribute(mlp_kernel,
                             cudaFuncAttributeMaxDynamicSharedMemorySize, SMEM_SZ);
        attr_set = true;
    }

    prep_weights_kernel<<<(NHID * 128 * 128 + 255) / 256, 256>>>(Wh);
    mlp_kernel<<<NTILES, THREADS, SMEM_SZ>>>(x, W0, b0, bh, Wout, bout, out);
}

// round 8
// speedup vs baseline: 2.7442x; 1.0020x over previous
#include <cuda_runtime.h>
#include <cuda_fp16.h>
#include <cstdint>

// ============================================================================
// NSFPRawMLP: x[262144,3] -> 128 -> (7x 128x128 + ReLU) -> 3
// R8: single-product fp16 GEMM, 32 rows/warp (two m16 A-tiles share every
// ldmatrix'd B fragment -> SMEM crossbar traffic per row halved; tensor pipe
// becomes the binding resource). 128 thr / 128 rows per CTA, 2 CTAs/SM,
// double-buffered weights.
// ============================================================================

#define NROWS   262144
#define NHID    7
#define ROWS_PER_CTA 128
#define NTILES  (NROWS / ROWS_PER_CTA)   // 2048 CTAs
#define THREADS 128                      // 4 warps, 32 rows/warp

// Weight images: [layer][32768 B] fp16.
// byte = n*256 + ((chunk ^ (n&7))<<4) + (k&7)*2, chunk = k>>3  (XOR swizzle)
static __device__ __align__(128) unsigned char g_wimg[NHID][32768];

// ---------------------------------------------------------------------------
// SMEM layout (dynamic): TWO weight buffers + small params (~72.7KB -> 2 CTA/SM)
// ---------------------------------------------------------------------------
#define SM_WBUF    0                     // 2 x 32768 = 65536
#define SM_BIAS    65536                 // 7*128 f32 = 3584
#define SM_W0      (SM_BIAS + 3584)      // 128*3 f32 = 1536
#define SM_B0      (SM_W0 + 1536)        // 128 f32  = 512
#define SM_WOUT    (SM_B0 + 512)         // 3*128 f32 = 1536
#define SM_BOUT    (SM_WOUT + 1536)      // 16
#define SMEM_SZ    (SM_BOUT + 16)        // 72,720 B

// ---------------------------------------------------------------------------
// PTX helpers (base-target, sm_80+)
// ---------------------------------------------------------------------------
__device__ __forceinline__ uint32_t smem_u32(const void* p) {
    uint32_t a;
    asm("{ .reg .u64 t; cvta.to.shared.u64 t, %1; cvt.u32.u64 %0, t; }"
        : "=r"(a) : "l"(p));
    return a;
}

#define CP_ASYNC16(dst_u32, src_ptr) \
    asm volatile("cp.async.cg.shared.global [%0], [%1], 16;" \
                 :: "r"(dst_u32), "l"(src_ptr) : "memory")
#define CP_COMMIT() asm volatile("cp.async.commit_group;" ::: "memory")
#define CP_WAIT(n)  asm volatile("cp.async.wait_group %0;" :: "n"(n) : "memory")

#define LDSM4(r0, r1, r2, r3, addr) \
    asm volatile("ldmatrix.sync.aligned.m8n8.x4.shared.b16 {%0,%1,%2,%3}, [%4];" \
                 : "=r"(r0), "=r"(r1), "=r"(r2), "=r"(r3) : "r"(addr))

#define MMA16816(C, A, b0_, b1_) \
    asm volatile("mma.sync.aligned.m16n8k16.row.col.f32.f16.f16.f32 " \
                 "{%0,%1,%2,%3},{%4,%5,%6,%7},{%8,%9},{%0,%1,%2,%3};" \
                 : "+f"((C)[0]), "+f"((C)[1]), "+f"((C)[2]), "+f"((C)[3]) \
                 : "r"((A)[0]), "r"((A)[1]), "r"((A)[2]), "r"((A)[3]), \
                   "r"(b0_), "r"(b1_))

// pack two fp32 -> fp16x2 (round-to-nearest)
__device__ __forceinline__ uint32_t pack_f16(float v0, float v1) {
    uint32_t r;
    asm("cvt.rn.f16x2.f32 %0, %1, %2;" : "=r"(r) : "f"(v1), "f"(v0));
    return r;
}

__device__ __forceinline__ float relu(float v) { return fmaxf(v, 0.0f); }

// ---------------------------------------------------------------------------
// Prep kernel: Wh fp32 -> fp16 swizzled image.
// ---------------------------------------------------------------------------
__global__ void prep_weights_kernel(const float* __restrict__ Wh) {
    int idx = blockIdx.x * blockDim.x + threadIdx.x;
    if (idx >= NHID * 128 * 128) return;
    int l = idx >> 14;
    int n = (idx >> 7) & 127;     // out feature
    int k = idx & 127;            // in feature
    __half w = __float2half_rn(Wh[idx]);
    uint32_t chunk = (uint32_t)k >> 3;
    uint32_t off = (uint32_t)n * 256 + ((chunk ^ ((uint32_t)n & 7)) << 4)
                 + ((uint32_t)k & 7) * 2;
    *(__half*)&g_wimg[l][off] = w;
}

// issue cp.async prefetch of one 32KB layer image into buf[layer&1]
__device__ __forceinline__ void prefetch_layer(uint32_t sb, int layer, int tid) {
    const char* src = (const char*)&g_wimg[layer][0];
    uint32_t dst = sb + SM_WBUF + (uint32_t)(layer & 1) * 32768;
    #pragma unroll
    for (int i = 0; i < 16; i++)
        CP_ASYNC16(dst + (uint32_t)(tid + i * THREADS) * 16,
                   src + (size_t)(tid + i * THREADS) * 16);
    CP_COMMIT();
}

// ---------------------------------------------------------------------------
// Main kernel: 128 rows per CTA, 4 warps (32 rows each), 2 CTAs per SM.
// ---------------------------------------------------------------------------
__global__ void __launch_bounds__(THREADS, 2)
mlp_kernel(const float* __restrict__ x,
           const float* __restrict__ W0,
           const float* __restrict__ b0,
           const float* __restrict__ bh,
           const float* __restrict__ Wout,
           const float* __restrict__ bout,
           float* __restrict__ out) {
    extern __shared__ char smem[];
    const uint32_t sb = smem_u32(smem);
    const int tid  = threadIdx.x;
    const int wid  = tid >> 5;
    const int lane = tid & 31;
    const int q    = lane & 3;          // quad index (col pair selector)

    // ---- layer-0 weights in flight before any compute ----
    prefetch_layer(sb, 0, tid);

    // ---- stage small params ----
    {
        float* bias_s = (float*)(smem + SM_BIAS);
        for (int i = tid; i < NHID * 128; i += THREADS) bias_s[i] = bh[i];
        if (tid < 128) {
            float* w0s = (float*)(smem + SM_W0);
            w0s[tid * 3 + 0] = W0[tid * 3 + 0];
            w0s[tid * 3 + 1] = W0[tid * 3 + 1];
            w0s[tid * 3 + 2] = W0[tid * 3 + 2];
            ((float*)(smem + SM_B0))[tid] = b0[tid];
        }
        float* wos = (float*)(smem + SM_WOUT);
        for (int i = tid; i < 384; i += THREADS) wos[i] = Wout[i];
        if (tid < 3) ((float*)(smem + SM_BOUT))[tid] = bout[tid];
    }
    __syncthreads();

    // global rows owned by this thread: 4 rows, two m16 tiles (a: g0,g1  b: g2,g3)
    const int rbase = blockIdx.x * ROWS_PER_CTA + wid * 32 + (lane >> 2);
    const int g0 = rbase;         // tile a, row lane/4
    const int g1 = rbase + 8;     // tile a, row lane/4 + 8
    const int g2 = rbase + 16;    // tile b
    const int g3 = rbase + 24;    // tile b

    // ---- layer 0: [3 -> 128] in fp32 FFMA, produce fp16 A fragments ----
    uint32_t Aa[8][4], Ab[8][4];
    {
        const float x00 = x[g0 * 3 + 0], x01 = x[g0 * 3 + 1], x02 = x[g0 * 3 + 2];
        const float x10 = x[g1 * 3 + 0], x11 = x[g1 * 3 + 1], x12 = x[g1 * 3 + 2];
        const float x20 = x[g2 * 3 + 0], x21 = x[g2 * 3 + 1], x22 = x[g2 * 3 + 2];
        const float x30 = x[g3 * 3 + 0], x31 = x[g3 * 3 + 1], x32 = x[g3 * 3 + 2];
        const float* w0s = (const float*)(smem + SM_W0);
        const float* b0s = (const float*)(smem + SM_B0);
        #pragma unroll
        for (int s = 0; s < 8; s++) {
            const int c0 = 16 * s + 2 * q;
            #pragma unroll
            for (int h = 0; h < 2; h++) {
                const int ca = c0 + 8 * h;
                const float wa0 = w0s[ca * 3 + 0], wa1 = w0s[ca * 3 + 1], wa2 = w0s[ca * 3 + 2];
                const float wb0 = w0s[(ca + 1) * 3 + 0], wb1 = w0s[(ca + 1) * 3 + 1], wb2 = w0s[(ca + 1) * 3 + 2];
                const float ba = b0s[ca], bb = b0s[ca + 1];
                float v00 = relu(fmaf(x00, wa0, fmaf(x01, wa1, fmaf(x02, wa2, ba))));
                float v01 = relu(fmaf(x00, wb0, fmaf(x01, wb1, fmaf(x02, wb2, bb))));
                float v10 = relu(fmaf(x10, wa0, fmaf(x11, wa1, fmaf(x12, wa2, ba))));
                float v11 = relu(fmaf(x10, wb0, fmaf(x11, wb1, fmaf(x12, wb2, bb))));
                Aa[s][2 * h + 0] = pack_f16(v00, v01);
                Aa[s][2 * h + 1] = pack_f16(v10, v11);
                float v20 = relu(fmaf(x20, wa0, fmaf(x21, wa1, fmaf(x22, wa2, ba))));
                float v21 = relu(fmaf(x20, wb0, fmaf(x21, wb1, fmaf(x22, wb2, bb))));
                float v30 = relu(fmaf(x30, wa0, fmaf(x31, wa1, fmaf(x32, wa2, ba))));
                float v31 = relu(fmaf(x30, wb0, fmaf(x31, wb1, fmaf(x32, wb2, bb))));
                Ab[s][2 * h + 0] = pack_f16(v20, v21);
                Ab[s][2 * h + 1] = pack_f16(v30, v31);
            }
        }
    }

    // per-thread ldmatrix address pieces
    const uint32_t nloc = (uint32_t)((lane & 7) + ((lane >> 4) & 1) * 8); // 0..15
    const uint32_t jbit = (uint32_t)((lane >> 3) & 1);                   // chunk +1
    uint32_t swz[8];
    #pragma unroll
    for (int s = 0; s < 8; s++)
        swz[s] = nloc * 256 + ((((uint32_t)(2 * s) + jbit) ^ (nloc & 7)) << 4);

    const float* bias_s = (const float*)(smem + SM_BIAS);
    const float* wout_s = (const float*)(smem + SM_WOUT);
    const float* bout_s = (const float*)(smem + SM_BOUT);

    // wait for layer-0 weights
    CP_WAIT(0);
    __syncthreads();

    // ---- 7 hidden layers, double-buffered weights ----
    #pragma unroll 1
    for (int l = 0; l < NHID; l++) {
        // buf[(l+1)&1] is free: refill now, overlapped with this whole layer.
        if (l + 1 < NHID) prefetch_layer(sb, l + 1, tid);

        const uint32_t wb = sb + SM_WBUF + (uint32_t)(l & 1) * 32768;

        float Ca[16][4], Cb[16][4];
        #pragma unroll
        for (int g = 0; g < 16; g++) {
            Ca[g][0] = 0.f; Ca[g][1] = 0.f; Ca[g][2] = 0.f; Ca[g][3] = 0.f;
            Cb[g][0] = 0.f; Cb[g][1] = 0.f; Cb[g][2] = 0.f; Cb[g][3] = 0.f;
        }

        #pragma unroll
        for (int s = 0; s < 8; s++) {
            const uint32_t base = wb + swz[s];
            #pragma unroll
            for (int pp = 0; pp < 4; pp++) {
                const uint32_t a0 = base + (uint32_t)(2 * pp) * 4096;
                const uint32_t a1 = a0 + 4096;
                uint32_t h0, h1, h2, h3, h4, h5, h6, h7;
                LDSM4(h0, h1, h2, h3, a0);             // W16 p=2pp
                LDSM4(h4, h5, h6, h7, a1);             // W16 p=2pp+1
                // each B fragment feeds BOTH A tiles (2x reuse)
                MMA16816(Ca[4 * pp + 0], Aa[s], h0, h1);
                MMA16816(Cb[4 * pp + 0], Ab[s], h0, h1);
                MMA16816(Ca[4 * pp + 1], Aa[s], h2, h3);
                MMA16816(Cb[4 * pp + 1], Ab[s], h2, h3);
                MMA16816(Ca[4 * pp + 2], Aa[s], h4, h5);
                MMA16816(Cb[4 * pp + 2], Ab[s], h4, h5);
                MMA16816(Ca[4 * pp + 3], Aa[s], h6, h7);
                MMA16816(Cb[4 * pp + 3], Ab[s], h6, h7);
            }
        }

        const float* bl = bias_s + l * 128;

        if (l < NHID - 1) {
            // bias + relu + fp16 quantize -> next layer A fragments
            #pragma unroll
            for (int s = 0; s < 8; s++) {
                const float2 bb0 = *(const float2*)&bl[16 * s + 2 * q];
                const float2 bb1 = *(const float2*)&bl[16 * s + 8 + 2 * q];
                Aa[s][0] = pack_f16(relu(Ca[2 * s][0] + bb0.x), relu(Ca[2 * s][1] + bb0.y));
                Aa[s][1] = pack_f16(relu(Ca[2 * s][2] + bb0.x), relu(Ca[2 * s][3] + bb0.y));
                Aa[s][2] = pack_f16(relu(Ca[2 * s + 1][0] + bb1.x), relu(Ca[2 * s + 1][1] + bb1.y));
                Aa[s][3] = pack_f16(relu(Ca[2 * s + 1][2] + bb1.x), relu(Ca[2 * s + 1][3] + bb1.y));
                Ab[s][0] = pack_f16(relu(Cb[2 * s][0] + bb0.x), relu(Cb[2 * s][1] + bb0.y));
                Ab[s][1] = pack_f16(relu(Cb[2 * s][2] + bb0.x), relu(Cb[2 * s][3] + bb0.y));
                Ab[s][2] = pack_f16(relu(Cb[2 * s + 1][0] + bb1.x), relu(Cb[2 * s + 1][1] + bb1.y));
                Ab[s][3] = pack_f16(relu(Cb[2 * s + 1][2] + bb1.x), relu(Cb[2 * s + 1][3] + bb1.y));
            }
            CP_WAIT(0);        // next layer's weights landed
            __syncthreads();   // all warps done with buf[l&1]; buf[(l+1)&1] visible
        } else {
            // final: bias + relu, fused [128 -> 3] projection + bout (4 rows)
            float o00 = 0.f, o01 = 0.f, o02 = 0.f;   // row g0
            float o10 = 0.f, o11 = 0.f, o12 = 0.f;   // row g1
            float o20 = 0.f, o21 = 0.f, o22 = 0.f;   // row g2
            float o30 = 0.f, o31 = 0.f, o32 = 0.f;   // row g3
            #pragma unroll
            for (int g = 0; g < 16; g++) {
                const int c = 8 * g + 2 * q;
                const float2 bb = *(const float2*)&bl[c];
                const float2 wj0 = *(const float2*)&wout_s[0 * 128 + c];
                const float2 wj1 = *(const float2*)&wout_s[1 * 128 + c];
                const float2 wj2 = *(const float2*)&wout_s[2 * 128 + c];
                float v00 = relu(Ca[g][0] + bb.x), v01 = relu(Ca[g][1] + bb.y);
                float v10 = relu(Ca[g][2] + bb.x), v11 = relu(Ca[g][3] + bb.y);
                float v20 = relu(Cb[g][0] + bb.x), v21 = relu(Cb[g][1] + bb.y);
                float v30 = relu(Cb[g][2] + bb.x), v31 = relu(Cb[g][3] + bb.y);
                o00 = fmaf(v00, wj0.x, fmaf(v01, wj0.y, o00));
                o01 = fmaf(v00, wj1.x, fmaf(v01, wj1.y, o01));
                o02 = fmaf(v00, wj2.x, fmaf(v01, wj2.y, o02));
                o10 = fmaf(v10, wj0.x, fmaf(v11, wj0.y, o10));
                o11 = fmaf(v10, wj1.x, fmaf(v11, wj1.y, o11));
                o12 = fmaf(v10, wj2.x, fmaf(v11, wj2.y, o12));
                o20 = fmaf(v20, wj0.x, fmaf(v21, wj0.y, o20));
                o21 = fmaf(v20, wj1.x, fmaf(v21, wj1.y, o21));
                o22 = fmaf(v20, wj2.x, fmaf(v21, wj2.y, o22));
                o30 = fmaf(v30, wj0.x, fmaf(v31, wj0.y, o30));
                o31 = fmaf(v30, wj1.x, fmaf(v31, wj1.y, o31));
                o32 = fmaf(v30, wj2.x, fmaf(v31, wj2.y, o32));
            }
            #pragma unroll
            for (int d = 1; d <= 2; d <<= 1) {
                o00 += __shfl_xor_sync(0xFFFFFFFF, o00, d);
                o01 += __shfl_xor_sync(0xFFFFFFFF, o01, d);
                o02 += __shfl_xor_sync(0xFFFFFFFF, o02, d);
                o10 += __shfl_xor_sync(0xFFFFFFFF, o10, d);
                o11 += __shfl_xor_sync(0xFFFFFFFF, o11, d);
                o12 += __shfl_xor_sync(0xFFFFFFFF, o12, d);
                o20 += __shfl_xor_sync(0xFFFFFFFF, o20, d);
                o21 += __shfl_xor_sync(0xFFFFFFFF, o21, d);
                o22 += __shfl_xor_sync(0xFFFFFFFF, o22, d);
                o30 += __shfl_xor_sync(0xFFFFFFFF, o30, d);
                o31 += __shfl_xor_sync(0xFFFFFFFF, o31, d);
                o32 += __shfl_xor_sync(0xFFFFFFFF, o32, d);
            }
            if (q == 0) {
                out[g0 * 3 + 0] = o00 + bout_s[0];
                out[g0 * 3 + 1] = o01 + bout_s[1];
                out[g0 * 3 + 2] = o02 + bout_s[2];
                out[g1 * 3 + 0] = o10 + bout_s[0];
                out[g1 * 3 + 1] = o11 + bout_s[1];
                out[g1 * 3 + 2] = o12 + bout_s[2];
                out[g2 * 3 + 0] = o20 + bout_s[0];
                out[g2 * 3 + 1] = o21 + bout_s[1];
                out[g2 * 3 + 2] = o22 + bout_s[2];
                out[g3 * 3 + 0] = o30 + bout_s[0];
                out[g3 * 3 + 1] = o31 + bout_s[1];
                out[g3 * 3 + 2] = o32 + bout_s[2];
            }
        }
    }
}

// ---------------------------------------------------------------------------
// kernel_launch
// ---------------------------------------------------------------------------
extern "C" void kernel_launch(void* const* d_in, const int* in_sizes, int n_in,
                              void* d_out, int out_size) {
    const float* x    = (const float*)d_in[0];   // [262144,3]
    const float* W0   = (const float*)d_in[1];   // [128,3]
    const float* b0   = (const float*)d_in[2];   // [128]
    const float* Wh   = (const float*)d_in[3];   // [7,128,128]
    const float* bh   = (const float*)d_in[4];   // [7,128]
    const float* Wout = (const float*)d_in[5];   // [3,128]
    const float* bout = (const float*)d_in[6];   // [3]
    float* out = (float*)d_out;                  // [262144,3]

    static bool attr_set = false;
    if (!attr_set) {
        cudaFuncSetAttribute(mlp_kernel,
                             cudaFuncAttributeMaxDynamicSharedMemorySize, SMEM_SZ);
        attr_set = true;
    }

    prep_weights_kernel<<<(NHID * 128 * 128 + 255) / 256, 256>>>(Wh);
    mlp_kernel<<<NTILES, THREADS, SMEM_SZ>>>(x, W0, b0, bh, Wout, bout, out);
}

// round 9
// speedup vs baseline: 2.7594x; 1.0056x over previous
#include <cuda_runtime.h>
#include <cuda_fp16.h>
#include <cstdint>

// ============================================================================
// NSFPRawMLP: x[262144,3] -> 128 -> (7x 128x128 + ReLU) -> 3
// R9: R8 + software-pipelined ldmatrix (one pp-group lookahead, h[2][8])
// so LDSM->MMA latency hides behind the previous group's 8 HMMAs.
// single-product fp16, 32 rows/warp, 128 thr / 128 rows per CTA, 2 CTAs/SM.
// ============================================================================

#define NROWS   262144
#define NHID    7
#define ROWS_PER_CTA 128
#define NTILES  (NROWS / ROWS_PER_CTA)   // 2048 CTAs
#define THREADS 128                      // 4 warps, 32 rows/warp

// Weight images: [layer][32768 B] fp16.
// byte = n*256 + ((chunk ^ (n&7))<<4) + (k&7)*2, chunk = k>>3  (XOR swizzle)
static __device__ __align__(128) unsigned char g_wimg[NHID][32768];

// ---------------------------------------------------------------------------
// SMEM layout (dynamic): TWO weight buffers + small params
// ---------------------------------------------------------------------------
#define SM_WBUF    0                     // 2 x 32768 = 65536
#define SM_BIAS    65536                 // 7*128 f32 = 3584
#define SM_W0      (SM_BIAS + 3584)      // 128*3 f32 = 1536
#define SM_B0      (SM_W0 + 1536)        // 128 f32  = 512
#define SM_WOUT    (SM_B0 + 512)         // 3*128 f32 = 1536
#define SM_BOUT    (SM_WOUT + 1536)      // 16
#define SMEM_SZ    (SM_BOUT + 16)        // 72,720 B

// ---------------------------------------------------------------------------
// PTX helpers (base-target, sm_80+)
// ---------------------------------------------------------------------------
__device__ __forceinline__ uint32_t smem_u32(const void* p) {
    uint32_t a;
    asm("{ .reg .u64 t; cvta.to.shared.u64 t, %1; cvt.u32.u64 %0, t; }"
        : "=r"(a) : "l"(p));
    return a;
}

#define CP_ASYNC16(dst_u32, src_ptr) \
    asm volatile("cp.async.cg.shared.global [%0], [%1], 16;" \
                 :: "r"(dst_u32), "l"(src_ptr) : "memory")
#define CP_COMMIT() asm volatile("cp.async.commit_group;" ::: "memory")
#define CP_WAIT(n)  asm volatile("cp.async.wait_group %0;" :: "n"(n) : "memory")

#define LDSM4(r0, r1, r2, r3, addr) \
    asm volatile("ldmatrix.sync.aligned.m8n8.x4.shared.b16 {%0,%1,%2,%3}, [%4];" \
                 : "=r"(r0), "=r"(r1), "=r"(r2), "=r"(r3) : "r"(addr))

#define MMA16816(C, A, b0_, b1_) \
    asm volatile("mma.sync.aligned.m16n8k16.row.col.f32.f16.f16.f32 " \
                 "{%0,%1,%2,%3},{%4,%5,%6,%7},{%8,%9},{%0,%1,%2,%3};" \
                 : "+f"((C)[0]), "+f"((C)[1]), "+f"((C)[2]), "+f"((C)[3]) \
                 : "r"((A)[0]), "r"((A)[1]), "r"((A)[2]), "r"((A)[3]), \
                   "r"(b0_), "r"(b1_))

// pack two fp32 -> fp16x2 (round-to-nearest)
__device__ __forceinline__ uint32_t pack_f16(float v0, float v1) {
    uint32_t r;
    asm("cvt.rn.f16x2.f32 %0, %1, %2;" : "=r"(r) : "f"(v1), "f"(v0));
    return r;
}

__device__ __forceinline__ float relu(float v) { return fmaxf(v, 0.0f); }

// ---------------------------------------------------------------------------
// Prep kernel: Wh fp32 -> fp16 swizzled image.
// ---------------------------------------------------------------------------
__global__ void prep_weights_kernel(const float* __restrict__ Wh) {
    int idx = blockIdx.x * blockDim.x + threadIdx.x;
    if (idx >= NHID * 128 * 128) return;
    int l = idx >> 14;
    int n = (idx >> 7) & 127;     // out feature
    int k = idx & 127;            // in feature
    __half w = __float2half_rn(Wh[idx]);
    uint32_t chunk = (uint32_t)k >> 3;
    uint32_t off = (uint32_t)n * 256 + ((chunk ^ ((uint32_t)n & 7)) << 4)
                 + ((uint32_t)k & 7) * 2;
    *(__half*)&g_wimg[l][off] = w;
}

// issue cp.async prefetch of one 32KB layer image into buf[layer&1]
__device__ __forceinline__ void prefetch_layer(uint32_t sb, int layer, int tid) {
    const char* src = (const char*)&g_wimg[layer][0];
    uint32_t dst = sb + SM_WBUF + (uint32_t)(layer & 1) * 32768;
    #pragma unroll
    for (int i = 0; i < 16; i++)
        CP_ASYNC16(dst + (uint32_t)(tid + i * THREADS) * 16,
                   src + (size_t)(tid + i * THREADS) * 16);
    CP_COMMIT();
}

// ---------------------------------------------------------------------------
// Main kernel: 128 rows per CTA, 4 warps (32 rows each), 2 CTAs per SM.
// ---------------------------------------------------------------------------
__global__ void __launch_bounds__(THREADS, 2)
mlp_kernel(const float* __restrict__ x,
           const float* __restrict__ W0,
           const float* __restrict__ b0,
           const float* __restrict__ bh,
           const float* __restrict__ Wout,
           const float* __restrict__ bout,
           float* __restrict__ out) {
    extern __shared__ char smem[];
    const uint32_t sb = smem_u32(smem);
    const int tid  = threadIdx.x;
    const int wid  = tid >> 5;
    const int lane = tid & 31;
    const int q    = lane & 3;          // quad index (col pair selector)

    // ---- layer-0 weights in flight before any compute ----
    prefetch_layer(sb, 0, tid);

    // ---- stage small params ----
    {
        float* bias_s = (float*)(smem + SM_BIAS);
        for (int i = tid; i < NHID * 128; i += THREADS) bias_s[i] = bh[i];
        if (tid < 128) {
            float* w0s = (float*)(smem + SM_W0);
            w0s[tid * 3 + 0] = W0[tid * 3 + 0];
            w0s[tid * 3 + 1] = W0[tid * 3 + 1];
            w0s[tid * 3 + 2] = W0[tid * 3 + 2];
            ((float*)(smem + SM_B0))[tid] = b0[tid];
        }
        float* wos = (float*)(smem + SM_WOUT);
        for (int i = tid; i < 384; i += THREADS) wos[i] = Wout[i];
        if (tid < 3) ((float*)(smem + SM_BOUT))[tid] = bout[tid];
    }
    __syncthreads();

    // global rows owned by this thread: 4 rows, two m16 tiles (a: g0,g1  b: g2,g3)
    const int rbase = blockIdx.x * ROWS_PER_CTA + wid * 32 + (lane >> 2);
    const int g0 = rbase;         // tile a
    const int g1 = rbase + 8;     // tile a
    const int g2 = rbase + 16;    // tile b
    const int g3 = rbase + 24;    // tile b

    // ---- layer 0: [3 -> 128] in fp32 FFMA, produce fp16 A fragments ----
    uint32_t Aa[8][4], Ab[8][4];
    {
        const float x00 = x[g0 * 3 + 0], x01 = x[g0 * 3 + 1], x02 = x[g0 * 3 + 2];
        const float x10 = x[g1 * 3 + 0], x11 = x[g1 * 3 + 1], x12 = x[g1 * 3 + 2];
        const float x20 = x[g2 * 3 + 0], x21 = x[g2 * 3 + 1], x22 = x[g2 * 3 + 2];
        const float x30 = x[g3 * 3 + 0], x31 = x[g3 * 3 + 1], x32 = x[g3 * 3 + 2];
        const float* w0s = (const float*)(smem + SM_W0);
        const float* b0s = (const float*)(smem + SM_B0);
        #pragma unroll
        for (int s = 0; s < 8; s++) {
            const int c0 = 16 * s + 2 * q;
            #pragma unroll
            for (int h = 0; h < 2; h++) {
                const int ca = c0 + 8 * h;
                const float wa0 = w0s[ca * 3 + 0], wa1 = w0s[ca * 3 + 1], wa2 = w0s[ca * 3 + 2];
                const float wb0 = w0s[(ca + 1) * 3 + 0], wb1 = w0s[(ca + 1) * 3 + 1], wb2 = w0s[(ca + 1) * 3 + 2];
                const float ba = b0s[ca], bb = b0s[ca + 1];
                float v00 = relu(fmaf(x00, wa0, fmaf(x01, wa1, fmaf(x02, wa2, ba))));
                float v01 = relu(fmaf(x00, wb0, fmaf(x01, wb1, fmaf(x02, wb2, bb))));
                float v10 = relu(fmaf(x10, wa0, fmaf(x11, wa1, fmaf(x12, wa2, ba))));
                float v11 = relu(fmaf(x10, wb0, fmaf(x11, wb1, fmaf(x12, wb2, bb))));
                Aa[s][2 * h + 0] = pack_f16(v00, v01);
                Aa[s][2 * h + 1] = pack_f16(v10, v11);
                float v20 = relu(fmaf(x20, wa0, fmaf(x21, wa1, fmaf(x22, wa2, ba))));
                float v21 = relu(fmaf(x20, wb0, fmaf(x21, wb1, fmaf(x22, wb2, bb))));
                float v30 = relu(fmaf(x30, wa0, fmaf(x31, wa1, fmaf(x32, wa2, ba))));
                float v31 = relu(fmaf(x30, wb0, fmaf(x31, wb1, fmaf(x32, wb2, bb))));
                Ab[s][2 * h + 0] = pack_f16(v20, v21);
                Ab[s][2 * h + 1] = pack_f16(v30, v31);
            }
        }
    }

    // per-thread ldmatrix address pieces
    const uint32_t nloc = (uint32_t)((lane & 7) + ((lane >> 4) & 1) * 8); // 0..15
    const uint32_t jbit = (uint32_t)((lane >> 3) & 1);                   // chunk +1
    uint32_t swz[8];
    #pragma unroll
    for (int s = 0; s < 8; s++)
        swz[s] = nloc * 256 + ((((uint32_t)(2 * s) + jbit) ^ (nloc & 7)) << 4);

    const float* bias_s = (const float*)(smem + SM_BIAS);
    const float* wout_s = (const float*)(smem + SM_WOUT);
    const float* bout_s = (const float*)(smem + SM_BOUT);

    // wait for layer-0 weights
    CP_WAIT(0);
    __syncthreads();

    // ---- 7 hidden layers, double-buffered weights + pipelined LDSM ----
    #pragma unroll 1
    for (int l = 0; l < NHID; l++) {
        // buf[(l+1)&1] is free: refill now, overlapped with this whole layer.
        if (l + 1 < NHID) prefetch_layer(sb, l + 1, tid);

        const uint32_t wb = sb + SM_WBUF + (uint32_t)(l & 1) * 32768;

        float Ca[16][4], Cb[16][4];
        #pragma unroll
        for (int g = 0; g < 16; g++) {
            Ca[g][0] = 0.f; Ca[g][1] = 0.f; Ca[g][2] = 0.f; Ca[g][3] = 0.f;
            Cb[g][0] = 0.f; Cb[g][1] = 0.f; Cb[g][2] = 0.f; Cb[g][3] = 0.f;
        }

        // 32 flat groups: grp = s*4 + pp. Double-buffered h frags (1 lookahead).
        uint32_t h[2][8];
        {   // prologue: load group 0
            const uint32_t a0 = wb + swz[0];
            LDSM4(h[0][0], h[0][1], h[0][2], h[0][3], a0);
            LDSM4(h[0][4], h[0][5], h[0][6], h[0][7], a0 + 4096);
        }
        #pragma unroll
        for (int grp = 0; grp < 32; grp++) {
            const int cur = grp & 1;
            const int nxt = cur ^ 1;
            if (grp + 1 < 32) {   // issue next group's LDSM before current MMAs
                const int s1 = (grp + 1) >> 2, pp1 = (grp + 1) & 3;
                const uint32_t a0 = wb + swz[s1] + (uint32_t)(2 * pp1) * 4096;
                LDSM4(h[nxt][0], h[nxt][1], h[nxt][2], h[nxt][3], a0);
                LDSM4(h[nxt][4], h[nxt][5], h[nxt][6], h[nxt][7], a0 + 4096);
            }
            const int s = grp >> 2, pp = grp & 3;
            MMA16816(Ca[4 * pp + 0], Aa[s], h[cur][0], h[cur][1]);
            MMA16816(Cb[4 * pp + 0], Ab[s], h[cur][0], h[cur][1]);
            MMA16816(Ca[4 * pp + 1], Aa[s], h[cur][2], h[cur][3]);
            MMA16816(Cb[4 * pp + 1], Ab[s], h[cur][2], h[cur][3]);
            MMA16816(Ca[4 * pp + 2], Aa[s], h[cur][4], h[cur][5]);
            MMA16816(Cb[4 * pp + 2], Ab[s], h[cur][4], h[cur][5]);
            MMA16816(Ca[4 * pp + 3], Aa[s], h[cur][6], h[cur][7]);
            MMA16816(Cb[4 * pp + 3], Ab[s], h[cur][6], h[cur][7]);
        }

        const float* bl = bias_s + l * 128;

        if (l < NHID - 1) {
            // bias + relu + fp16 quantize -> next layer A fragments
            #pragma unroll
            for (int s = 0; s < 8; s++) {
                const float2 bb0 = *(const float2*)&bl[16 * s + 2 * q];
                const float2 bb1 = *(const float2*)&bl[16 * s + 8 + 2 * q];
                Aa[s][0] = pack_f16(relu(Ca[2 * s][0] + bb0.x), relu(Ca[2 * s][1] + bb0.y));
                Aa[s][1] = pack_f16(relu(Ca[2 * s][2] + bb0.x), relu(Ca[2 * s][3] + bb0.y));
                Aa[s][2] = pack_f16(relu(Ca[2 * s + 1][0] + bb1.x), relu(Ca[2 * s + 1][1] + bb1.y));
                Aa[s][3] = pack_f16(relu(Ca[2 * s + 1][2] + bb1.x), relu(Ca[2 * s + 1][3] + bb1.y));
                Ab[s][0] = pack_f16(relu(Cb[2 * s][0] + bb0.x), relu(Cb[2 * s][1] + bb0.y));
                Ab[s][1] = pack_f16(relu(Cb[2 * s][2] + bb0.x), relu(Cb[2 * s][3] + bb0.y));
                Ab[s][2] = pack_f16(relu(Cb[2 * s + 1][0] + bb1.x), relu(Cb[2 * s + 1][1] + bb1.y));
                Ab[s][3] = pack_f16(relu(Cb[2 * s + 1][2] + bb1.x), relu(Cb[2 * s + 1][3] + bb1.y));
            }
            CP_WAIT(0);        // next layer's weights landed
            __syncthreads();   // all warps done with buf[l&1]; buf[(l+1)&1] visible
        } else {
            // final: bias + relu, fused [128 -> 3] projection + bout (4 rows)
            float o00 = 0.f, o01 = 0.f, o02 = 0.f;
            float o10 = 0.f, o11 = 0.f, o12 = 0.f;
            float o20 = 0.f, o21 = 0.f, o22 = 0.f;
            float o30 = 0.f, o31 = 0.f, o32 = 0.f;
            #pragma unroll
            for (int g = 0; g < 16; g++) {
                const int c = 8 * g + 2 * q;
                const float2 bb = *(const float2*)&bl[c];
                const float2 wj0 = *(const float2*)&wout_s[0 * 128 + c];
                const float2 wj1 = *(const float2*)&wout_s[1 * 128 + c];
                const float2 wj2 = *(const float2*)&wout_s[2 * 128 + c];
                float v00 = relu(Ca[g][0] + bb.x), v01 = relu(Ca[g][1] + bb.y);
                float v10 = relu(Ca[g][2] + bb.x), v11 = relu(Ca[g][3] + bb.y);
                float v20 = relu(Cb[g][0] + bb.x), v21 = relu(Cb[g][1] + bb.y);
                float v30 = relu(Cb[g][2] + bb.x), v31 = relu(Cb[g][3] + bb.y);
                o00 = fmaf(v00, wj0.x, fmaf(v01, wj0.y, o00));
                o01 = fmaf(v00, wj1.x, fmaf(v01, wj1.y, o01));
                o02 = fmaf(v00, wj2.x, fmaf(v01, wj2.y, o02));
                o10 = fmaf(v10, wj0.x, fmaf(v11, wj0.y, o10));
                o11 = fmaf(v10, wj1.x, fmaf(v11, wj1.y, o11));
                o12 = fmaf(v10, wj2.x, fmaf(v11, wj2.y, o12));
                o20 = fmaf(v20, wj0.x, fmaf(v21, wj0.y, o20));
                o21 = fmaf(v20, wj1.x, fmaf(v21, wj1.y, o21));
                o22 = fmaf(v20, wj2.x, fmaf(v21, wj2.y, o22));
                o30 = fmaf(v30, wj0.x, fmaf(v31, wj0.y, o30));
                o31 = fmaf(v30, wj1.x, fmaf(v31, wj1.y, o31));
                o32 = fmaf(v30, wj2.x, fmaf(v31, wj2.y, o32));
            }
            #pragma unroll
            for (int d = 1; d <= 2; d <<= 1) {
                o00 += __shfl_xor_sync(0xFFFFFFFF, o00, d);
                o01 += __shfl_xor_sync(0xFFFFFFFF, o01, d);
                o02 += __shfl_xor_sync(0xFFFFFFFF, o02, d);
                o10 += __shfl_xor_sync(0xFFFFFFFF, o10, d);
                o11 += __shfl_xor_sync(0xFFFFFFFF, o11, d);
                o12 += __shfl_xor_sync(0xFFFFFFFF, o12, d);
                o20 += __shfl_xor_sync(0xFFFFFFFF, o20, d);
                o21 += __shfl_xor_sync(0xFFFFFFFF, o21, d);
                o22 += __shfl_xor_sync(0xFFFFFFFF, o22, d);
                o30 += __shfl_xor_sync(0xFFFFFFFF, o30, d);
                o31 += __shfl_xor_sync(0xFFFFFFFF, o31, d);
                o32 += __shfl_xor_sync(0xFFFFFFFF, o32, d);
            }
            if (q == 0) {
                out[g0 * 3 + 0] = o00 + bout_s[0];
                out[g0 * 3 + 1] = o01 + bout_s[1];
                out[g0 * 3 + 2] = o02 + bout_s[2];
                out[g1 * 3 + 0] = o10 + bout_s[0];
                out[g1 * 3 + 1] = o11 + bout_s[1];
                out[g1 * 3 + 2] = o12 + bout_s[2];
                out[g2 * 3 + 0] = o20 + bout_s[0];
                out[g2 * 3 + 1] = o21 + bout_s[1];
                out[g2 * 3 + 2] = o22 + bout_s[2];
                out[g3 * 3 + 0] = o30 + bout_s[0];
                out[g3 * 3 + 1] = o31 + bout_s[1];
                out[g3 * 3 + 2] = o32 + bout_s[2];
            }
        }
    }
}

// ---------------------------------------------------------------------------
// kernel_launch
// ---------------------------------------------------------------------------
extern "C" void kernel_launch(void* const* d_in, const int* in_sizes, int n_in,
                              void* d_out, int out_size) {
    const float* x    = (const float*)d_in[0];   // [262144,3]
    const float* W0   = (const float*)d_in[1];   // [128,3]
    const float* b0   = (const float*)d_in[2];   // [128]
    const float* Wh   = (const float*)d_in[3];   // [7,128,128]
    const float* bh   = (const float*)d_in[4];   // [7,128]
    const float* Wout = (const float*)d_in[5];   // [3,128]
    const float* bout = (const float*)d_in[6];   // [3]
    float* out = (float*)d_out;                  // [262144,3]

    static bool attr_set = false;
    if (!attr_set) {
        cudaFuncSetAttribute(mlp_kernel,
                             cudaFuncAttributeMaxDynamicSharedMemorySize, SMEM_SZ);
        attr_set = true;
    }

    prep_weights_kernel<<<(NHID * 128 * 128 + 255) / 256, 256>>>(Wh);
    mlp_kernel<<<NTILES, THREADS, SMEM_SZ>>>(x, W0, b0, bh, Wout, bout, out);
}

// round 10
// speedup vs baseline: 3.1442x; 1.1394x over previous
#include <cuda_runtime.h>
#include <cuda_fp16.h>
#include <cstdint>

// ============================================================================
// NSFPRawMLP: x[262144,3] -> 128 -> (7x 128x128 + ReLU) -> 3
// R10: pp-outer mainloop -> per-n-block epilogue overlapped with next block's
// MMAs; f16x2 epilogue (pack -> hadd2 bias -> hmax2 relu, 3 ops/frag);
// single-product fp16, 32 rows/warp, 128 thr / 128 rows/CTA, 2 CTAs/SM,
// double-buffered weights.
// ============================================================================

#define NROWS   262144
#define NHID    7
#define ROWS_PER_CTA 128
#define NTILES  (NROWS / ROWS_PER_CTA)   // 2048 CTAs
#define THREADS 128                      // 4 warps, 32 rows/warp

// Weight images: [layer][32768 B] fp16.
// byte = n*256 + ((chunk ^ (n&7))<<4) + (k&7)*2, chunk = k>>3  (XOR swizzle)
static __device__ __align__(128) unsigned char g_wimg[NHID][32768];

// ---------------------------------------------------------------------------
// SMEM layout
// ---------------------------------------------------------------------------
#define SM_WBUF    0                     // 2 x 32768 = 65536
#define SM_BIAS    65536                 // 7*128 f32 = 3584
#define SM_BIASH   69120                 // 7*64 half2 = 1792
#define SM_W0      70912                 // 128*3 f32 = 1536
#define SM_B0      72448                 // 128 f32  = 512
#define SM_WOUT    72960                 // 3*128 f32 = 1536
#define SM_BOUT    74496                 // 16
#define SMEM_SZ    74512

// ---------------------------------------------------------------------------
// PTX helpers (base-target, sm_80+)
// ---------------------------------------------------------------------------
__device__ __forceinline__ uint32_t smem_u32(const void* p) {
    uint32_t a;
    asm("{ .reg .u64 t; cvta.to.shared.u64 t, %1; cvt.u32.u64 %0, t; }"
        : "=r"(a) : "l"(p));
    return a;
}

#define CP_ASYNC16(dst_u32, src_ptr) \
    asm volatile("cp.async.cg.shared.global [%0], [%1], 16;" \
                 :: "r"(dst_u32), "l"(src_ptr) : "memory")
#define CP_COMMIT() asm volatile("cp.async.commit_group;" ::: "memory")
#define CP_WAIT(n)  asm volatile("cp.async.wait_group %0;" :: "n"(n) : "memory")

#define LDSM4(r0, r1, r2, r3, addr) \
    asm volatile("ldmatrix.sync.aligned.m8n8.x4.shared.b16 {%0,%1,%2,%3}, [%4];" \
                 : "=r"(r0), "=r"(r1), "=r"(r2), "=r"(r3) : "r"(addr))

#define MMA16816(C, A, b0_, b1_) \
    asm volatile("mma.sync.aligned.m16n8k16.row.col.f32.f16.f16.f32 " \
                 "{%0,%1,%2,%3},{%4,%5,%6,%7},{%8,%9},{%0,%1,%2,%3};" \
                 : "+f"((C)[0]), "+f"((C)[1]), "+f"((C)[2]), "+f"((C)[3]) \
                 : "r"((A)[0]), "r"((A)[1]), "r"((A)[2]), "r"((A)[3]), \
                   "r"(b0_), "r"(b1_))

// pack two fp32 -> fp16x2 (round-to-nearest)
__device__ __forceinline__ uint32_t pack_f16(float v0, float v1) {
    uint32_t r;
    asm("cvt.rn.f16x2.f32 %0, %1, %2;" : "=r"(r) : "f"(v1), "f"(v0));
    return r;
}

__device__ __forceinline__ float relu(float v) { return fmaxf(v, 0.0f); }

// f16x2 epilogue op: pack(c0,c1) + bias2 (f16), relu via hmax2
__device__ __forceinline__ uint32_t epi_op(float c0, float c1, uint32_t b2) {
    uint32_t v = pack_f16(c0, c1);
    __half2 hv = __hadd2(*reinterpret_cast<__half2*>(&v),
                         *reinterpret_cast<const __half2*>(&b2));
    const __half2 z = __floats2half2_rn(0.f, 0.f);
    hv = __hmax2(hv, z);
    return *reinterpret_cast<uint32_t*>(&hv);
}

// epilogue for one 16-col s-group of one tile: C0/C1 are the two n8 tiles
__device__ __forceinline__ void epi_sg(uint32_t (&Aout)[4],
                                       const float (&C0)[4], const float (&C1)[4],
                                       uint32_t b20, uint32_t b21) {
    Aout[0] = epi_op(C0[0], C0[1], b20);
    Aout[1] = epi_op(C0[2], C0[3], b20);
    Aout[2] = epi_op(C1[0], C1[1], b21);
    Aout[3] = epi_op(C1[2], C1[3], b21);
}

// ---------------------------------------------------------------------------
// Prep kernel: Wh fp32 -> fp16 swizzled image.
// ---------------------------------------------------------------------------
__global__ void prep_weights_kernel(const float* __restrict__ Wh) {
    int idx = blockIdx.x * blockDim.x + threadIdx.x;
    if (idx >= NHID * 128 * 128) return;
    int l = idx >> 14;
    int n = (idx >> 7) & 127;     // out feature
    int k = idx & 127;            // in feature
    __half w = __float2half_rn(Wh[idx]);
    uint32_t chunk = (uint32_t)k >> 3;
    uint32_t off = (uint32_t)n * 256 + ((chunk ^ ((uint32_t)n & 7)) << 4)
                 + ((uint32_t)k & 7) * 2;
    *(__half*)&g_wimg[l][off] = w;
}

// issue cp.async prefetch of one 32KB layer image into buf[layer&1]
__device__ __forceinline__ void prefetch_layer(uint32_t sb, int layer, int tid) {
    const char* src = (const char*)&g_wimg[layer][0];
    uint32_t dst = sb + SM_WBUF + (uint32_t)(layer & 1) * 32768;
    #pragma unroll
    for (int i = 0; i < 16; i++)
        CP_ASYNC16(dst + (uint32_t)(tid + i * THREADS) * 16,
                   src + (size_t)(tid + i * THREADS) * 16);
    CP_COMMIT();
}

// ---------------------------------------------------------------------------
// One hidden layer: pp-outer k-loop, per-block epilogue overlapped.
// Aia/Aib: input fragments; Aoa/Aob: output fragments (f16 quantized).
// ---------------------------------------------------------------------------
__device__ __forceinline__ void hidden_layer(
    uint32_t wb, const uint32_t (&swz)[8], int q,
    uint32_t (&Aia)[8][4], uint32_t (&Aib)[8][4],
    uint32_t (&Aoa)[8][4], uint32_t (&Aob)[8][4],
    const uint32_t* __restrict__ b2) {
    float Ca[16][4], Cb[16][4];
    uint32_t h[2][8];
    LDSM4(h[0][0], h[0][1], h[0][2], h[0][3], wb + swz[0]);
    LDSM4(h[0][4], h[0][5], h[0][6], h[0][7], wb + swz[0] + 4096);
    #pragma unroll
    for (int grp = 0; grp < 32; grp++) {
        const int cur = grp & 1, nxt = cur ^ 1;
        const int pp = grp >> 3, s = grp & 7;
        if (grp + 1 < 32) {
            const int pp1 = (grp + 1) >> 3, s1 = (grp + 1) & 7;
            const uint32_t a0 = wb + swz[s1] + (uint32_t)(2 * pp1) * 4096;
            LDSM4(h[nxt][0], h[nxt][1], h[nxt][2], h[nxt][3], a0);
            LDSM4(h[nxt][4], h[nxt][5], h[nxt][6], h[nxt][7], a0 + 4096);
        }
        if (s == 0) {
            #pragma unroll
            for (int j = 0; j < 4; j++) {
                Ca[4 * pp + j][0] = 0.f; Ca[4 * pp + j][1] = 0.f;
                Ca[4 * pp + j][2] = 0.f; Ca[4 * pp + j][3] = 0.f;
                Cb[4 * pp + j][0] = 0.f; Cb[4 * pp + j][1] = 0.f;
                Cb[4 * pp + j][2] = 0.f; Cb[4 * pp + j][3] = 0.f;
            }
        }
        MMA16816(Ca[4 * pp + 0], Aia[s], h[cur][0], h[cur][1]);
        MMA16816(Cb[4 * pp + 0], Aib[s], h[cur][0], h[cur][1]);
        MMA16816(Ca[4 * pp + 1], Aia[s], h[cur][2], h[cur][3]);
        MMA16816(Cb[4 * pp + 1], Aib[s], h[cur][2], h[cur][3]);
        MMA16816(Ca[4 * pp + 2], Aia[s], h[cur][4], h[cur][5]);
        MMA16816(Cb[4 * pp + 2], Aib[s], h[cur][4], h[cur][5]);
        MMA16816(Ca[4 * pp + 3], Aia[s], h[cur][6], h[cur][7]);
        MMA16816(Cb[4 * pp + 3], Aib[s], h[cur][6], h[cur][7]);
        // previous block's epilogue, overlapped with this block's MMA stream
        if (s == 1 && pp > 0) {
            const int p0 = pp - 1;
            #pragma unroll
            for (int e = 0; e < 2; e++) {
                const int sg = 2 * p0 + e;
                const uint32_t b20 = b2[8 * sg + q];
                const uint32_t b21 = b2[8 * sg + 4 + q];
                epi_sg(Aoa[sg], Ca[2 * sg], Ca[2 * sg + 1], b20, b21);
                epi_sg(Aob[sg], Cb[2 * sg], Cb[2 * sg + 1], b20, b21);
            }
        }
    }
    // last block's epilogue (exposed, 1/4 of total)
    #pragma unroll
    for (int e = 0; e < 2; e++) {
        const int sg = 6 + e;
        const uint32_t b20 = b2[8 * sg + q];
        const uint32_t b21 = b2[8 * sg + 4 + q];
        epi_sg(Aoa[sg], Ca[2 * sg], Ca[2 * sg + 1], b20, b21);
        epi_sg(Aob[sg], Cb[2 * sg], Cb[2 * sg + 1], b20, b21);
    }
}

// ---------------------------------------------------------------------------
// Final layer: same kloop, per-block fp32 bias+relu+[128->3] projection.
// ---------------------------------------------------------------------------
__device__ __forceinline__ void final_layer(
    uint32_t wb, const uint32_t (&swz)[8], int q,
    uint32_t (&Aia)[8][4], uint32_t (&Aib)[8][4],
    const float* __restrict__ bl, const float* __restrict__ wout_s,
    float (&o)[12]) {
    float Ca[16][4], Cb[16][4];
    uint32_t h[2][8];
    LDSM4(h[0][0], h[0][1], h[0][2], h[0][3], wb + swz[0]);
    LDSM4(h[0][4], h[0][5], h[0][6], h[0][7], wb + swz[0] + 4096);
    #pragma unroll
    for (int grp = 0; grp < 32; grp++) {
        const int cur = grp & 1, nxt = cur ^ 1;
        const int pp = grp >> 3, s = grp & 7;
        if (grp + 1 < 32) {
            const int pp1 = (grp + 1) >> 3, s1 = (grp + 1) & 7;
            const uint32_t a0 = wb + swz[s1] + (uint32_t)(2 * pp1) * 4096;
            LDSM4(h[nxt][0], h[nxt][1], h[nxt][2], h[nxt][3], a0);
            LDSM4(h[nxt][4], h[nxt][5], h[nxt][6], h[nxt][7], a0 + 4096);
        }
        if (s == 0) {
            #pragma unroll
            for (int j = 0; j < 4; j++) {
                Ca[4 * pp + j][0] = 0.f; Ca[4 * pp + j][1] = 0.f;
                Ca[4 * pp + j][2] = 0.f; Ca[4 * pp + j][3] = 0.f;
                Cb[4 * pp + j][0] = 0.f; Cb[4 * pp + j][1] = 0.f;
                Cb[4 * pp + j][2] = 0.f; Cb[4 * pp + j][3] = 0.f;
            }
        }
        MMA16816(Ca[4 * pp + 0], Aia[s], h[cur][0], h[cur][1]);
        MMA16816(Cb[4 * pp + 0], Aib[s], h[cur][0], h[cur][1]);
        MMA16816(Ca[4 * pp + 1], Aia[s], h[cur][2], h[cur][3]);
        MMA16816(Cb[4 * pp + 1], Aib[s], h[cur][2], h[cur][3]);
        MMA16816(Ca[4 * pp + 2], Aia[s], h[cur][4], h[cur][5]);
        MMA16816(Cb[4 * pp + 2], Aib[s], h[cur][4], h[cur][5]);
        MMA16816(Ca[4 * pp + 3], Aia[s], h[cur][6], h[cur][7]);
        MMA16816(Cb[4 * pp + 3], Aib[s], h[cur][6], h[cur][7]);
        if (s == 1 && pp > 0) {
            const int p0 = pp - 1;
            #pragma unroll
            for (int g = 4 * p0; g < 4 * p0 + 4; g++) {
                const int c = 8 * g + 2 * q;
                const float2 bb  = *(const float2*)&bl[c];
                const float2 wj0 = *(const float2*)&wout_s[0 * 128 + c];
                const float2 wj1 = *(const float2*)&wout_s[1 * 128 + c];
                const float2 wj2 = *(const float2*)&wout_s[2 * 128 + c];
                float v00 = relu(Ca[g][0] + bb.x), v01 = relu(Ca[g][1] + bb.y);
                float v10 = relu(Ca[g][2] + bb.x), v11 = relu(Ca[g][3] + bb.y);
                float v20 = relu(Cb[g][0] + bb.x), v21 = relu(Cb[g][1] + bb.y);
                float v30 = relu(Cb[g][2] + bb.x), v31 = relu(Cb[g][3] + bb.y);
                o[0]  = fmaf(v00, wj0.x, fmaf(v01, wj0.y, o[0]));
                o[1]  = fmaf(v00, wj1.x, fmaf(v01, wj1.y, o[1]));
                o[2]  = fmaf(v00, wj2.x, fmaf(v01, wj2.y, o[2]));
                o[3]  = fmaf(v10, wj0.x, fmaf(v11, wj0.y, o[3]));
                o[4]  = fmaf(v10, wj1.x, fmaf(v11, wj1.y, o[4]));
                o[5]  = fmaf(v10, wj2.x, fmaf(v11, wj2.y, o[5]));
                o[6]  = fmaf(v20, wj0.x, fmaf(v21, wj0.y, o[6]));
                o[7]  = fmaf(v20, wj1.x, fmaf(v21, wj1.y, o[7]));
                o[8]  = fmaf(v20, wj2.x, fmaf(v21, wj2.y, o[8]));
                o[9]  = fmaf(v30, wj0.x, fmaf(v31, wj0.y, o[9]));
                o[10] = fmaf(v30, wj1.x, fmaf(v31, wj1.y, o[10]));
                o[11] = fmaf(v30, wj2.x, fmaf(v31, wj2.y, o[11]));
            }
        }
    }
    #pragma unroll
    for (int g = 12; g < 16; g++) {
        const int c = 8 * g + 2 * q;
        const float2 bb  = *(const float2*)&bl[c];
        const float2 wj0 = *(const float2*)&wout_s[0 * 128 + c];
        const float2 wj1 = *(const float2*)&wout_s[1 * 128 + c];
        const float2 wj2 = *(const float2*)&wout_s[2 * 128 + c];
        float v00 = relu(Ca[g][0] + bb.x), v01 = relu(Ca[g][1] + bb.y);
        float v10 = relu(Ca[g][2] + bb.x), v11 = relu(Ca[g][3] + bb.y);
        float v20 = relu(Cb[g][0] + bb.x), v21 = relu(Cb[g][1] + bb.y);
        float v30 = relu(Cb[g][2] + bb.x), v31 = relu(Cb[g][3] + bb.y);
        o[0]  = fmaf(v00, wj0.x, fmaf(v01, wj0.y, o[0]));
        o[1]  = fmaf(v00, wj1.x, fmaf(v01, wj1.y, o[1]));
        o[2]  = fmaf(v00, wj2.x, fmaf(v01, wj2.y, o[2]));
        o[3]  = fmaf(v10, wj0.x, fmaf(v11, wj0.y, o[3]));
        o[4]  = fmaf(v10, wj1.x, fmaf(v11, wj1.y, o[4]));
        o[5]  = fmaf(v10, wj2.x, fmaf(v11, wj2.y, o[5]));
        o[6]  = fmaf(v20, wj0.x, fmaf(v21, wj0.y, o[6]));
        o[7]  = fmaf(v20, wj1.x, fmaf(v21, wj1.y, o[7]));
        o[8]  = fmaf(v20, wj2.x, fmaf(v21, wj2.y, o[8]));
        o[9]  = fmaf(v30, wj0.x, fmaf(v31, wj0.y, o[9]));
        o[10] = fmaf(v30, wj1.x, fmaf(v31, wj1.y, o[10]));
        o[11] = fmaf(v30, wj2.x, fmaf(v31, wj2.y, o[11]));
    }
}

// ---------------------------------------------------------------------------
// Main kernel: 128 rows per CTA, 4 warps (32 rows each), 2 CTAs per SM.
// ---------------------------------------------------------------------------
__global__ void __launch_bounds__(THREADS, 2)
mlp_kernel(const float* __restrict__ x,
           const float* __restrict__ W0,
           const float* __restrict__ b0,
           const float* __restrict__ bh,
           const float* __restrict__ Wout,
           const float* __restrict__ bout,
           float* __restrict__ out) {
    extern __shared__ char smem[];
    const uint32_t sb = smem_u32(smem);
    const int tid  = threadIdx.x;
    const int wid  = tid >> 5;
    const int lane = tid & 31;
    const int q    = lane & 3;

    prefetch_layer(sb, 0, tid);

    // ---- stage small params ----
    {
        float* bias_s = (float*)(smem + SM_BIAS);
        for (int i = tid; i < NHID * 128; i += THREADS) bias_s[i] = bh[i];
        uint32_t* b2s = (uint32_t*)(smem + SM_BIASH);
        for (int i = tid; i < NHID * 64; i += THREADS)
            b2s[i] = pack_f16(bh[2 * i], bh[2 * i + 1]);
        if (tid < 128) {
            float* w0s = (float*)(smem + SM_W0);
            w0s[tid * 3 + 0] = W0[tid * 3 + 0];
            w0s[tid * 3 + 1] = W0[tid * 3 + 1];
            w0s[tid * 3 + 2] = W0[tid * 3 + 2];
            ((float*)(smem + SM_B0))[tid] = b0[tid];
        }
        float* wos = (float*)(smem + SM_WOUT);
        for (int i = tid; i < 384; i += THREADS) wos[i] = Wout[i];
        if (tid < 3) ((float*)(smem + SM_BOUT))[tid] = bout[tid];
    }
    __syncthreads();

    const int rbase = blockIdx.x * ROWS_PER_CTA + wid * 32 + (lane >> 2);
    const int g0 = rbase, g1 = rbase + 8, g2 = rbase + 16, g3 = rbase + 24;

    // ---- layer 0: [3 -> 128] fp32 FFMA -> fp16 A fragments ----
    uint32_t A0a[8][4], A0b[8][4], A1a[8][4], A1b[8][4];
    {
        const float x00 = x[g0 * 3 + 0], x01 = x[g0 * 3 + 1], x02 = x[g0 * 3 + 2];
        const float x10 = x[g1 * 3 + 0], x11 = x[g1 * 3 + 1], x12 = x[g1 * 3 + 2];
        const float x20 = x[g2 * 3 + 0], x21 = x[g2 * 3 + 1], x22 = x[g2 * 3 + 2];
        const float x30 = x[g3 * 3 + 0], x31 = x[g3 * 3 + 1], x32 = x[g3 * 3 + 2];
        const float* w0s = (const float*)(smem + SM_W0);
        const float* b0s = (const float*)(smem + SM_B0);
        #pragma unroll
        for (int s = 0; s < 8; s++) {
            const int c0 = 16 * s + 2 * q;
            #pragma unroll
            for (int h = 0; h < 2; h++) {
                const int ca = c0 + 8 * h;
                const float wa0 = w0s[ca * 3 + 0], wa1 = w0s[ca * 3 + 1], wa2 = w0s[ca * 3 + 2];
                const float wb0 = w0s[(ca + 1) * 3 + 0], wb1 = w0s[(ca + 1) * 3 + 1], wb2 = w0s[(ca + 1) * 3 + 2];
                const float ba = b0s[ca], bb = b0s[ca + 1];
                float v00 = relu(fmaf(x00, wa0, fmaf(x01, wa1, fmaf(x02, wa2, ba))));
                float v01 = relu(fmaf(x00, wb0, fmaf(x01, wb1, fmaf(x02, wb2, bb))));
                float v10 = relu(fmaf(x10, wa0, fmaf(x11, wa1, fmaf(x12, wa2, ba))));
                float v11 = relu(fmaf(x10, wb0, fmaf(x11, wb1, fmaf(x12, wb2, bb))));
                A0a[s][2 * h + 0] = pack_f16(v00, v01);
                A0a[s][2 * h + 1] = pack_f16(v10, v11);
                float v20 = relu(fmaf(x20, wa0, fmaf(x21, wa1, fmaf(x22, wa2, ba))));
                float v21 = relu(fmaf(x20, wb0, fmaf(x21, wb1, fmaf(x22, wb2, bb))));
                float v30 = relu(fmaf(x30, wa0, fmaf(x31, wa1, fmaf(x32, wa2, ba))));
                float v31 = relu(fmaf(x30, wb0, fmaf(x31, wb1, fmaf(x32, wb2, bb))));
                A0b[s][2 * h + 0] = pack_f16(v20, v21);
                A0b[s][2 * h + 1] = pack_f16(v30, v31);
            }
        }
    }

    // per-thread ldmatrix address pieces
    const uint32_t nloc = (uint32_t)((lane & 7) + ((lane >> 4) & 1) * 8);
    const uint32_t jbit = (uint32_t)((lane >> 3) & 1);
    uint32_t swz[8];
    #pragma unroll
    for (int s = 0; s < 8; s++)
        swz[s] = nloc * 256 + ((((uint32_t)(2 * s) + jbit) ^ (nloc & 7)) << 4);

    const float* bias_s = (const float*)(smem + SM_BIAS);
    const float* wout_s = (const float*)(smem + SM_WOUT);
    const float* bout_s = (const float*)(smem + SM_BOUT);
    const uint32_t* b2base = (const uint32_t*)(smem + SM_BIASH);

    CP_WAIT(0);
    __syncthreads();

    // ---- 6 hidden->hidden layers (A0->A1->A0...), double-buffered weights ----
    #pragma unroll 1
    for (int it = 0; it < 3; it++) {
        const int l0 = 2 * it;
        prefetch_layer(sb, l0 + 1, tid);
        hidden_layer(sb + SM_WBUF + (uint32_t)(l0 & 1) * 32768, swz, q,
                     A0a, A0b, A1a, A1b, b2base + l0 * 64);
        CP_WAIT(0);
        __syncthreads();
        prefetch_layer(sb, l0 + 2, tid);
        hidden_layer(sb + SM_WBUF + (uint32_t)((l0 + 1) & 1) * 32768, swz, q,
                     A1a, A1b, A0a, A0b, b2base + (l0 + 1) * 64);
        CP_WAIT(0);
        __syncthreads();
    }

    // ---- final layer (l=6, buf 0): MMA + fused [128->3] projection ----
    float o[12];
    #pragma unroll
    for (int i = 0; i < 12; i++) o[i] = 0.f;
    final_layer(sb + SM_WBUF, swz, q, A0a, A0b, bias_s + 6 * 128, wout_s, o);

    #pragma unroll
    for (int d = 1; d <= 2; d <<= 1) {
        #pragma unroll
        for (int i = 0; i < 12; i++)
            o[i] += __shfl_xor_sync(0xFFFFFFFF, o[i], d);
    }
    if (q == 0) {
        out[g0 * 3 + 0] = o[0] + bout_s[0];
        out[g0 * 3 + 1] = o[1] + bout_s[1];
        out[g0 * 3 + 2] = o[2] + bout_s[2];
        out[g1 * 3 + 0] = o[3] + bout_s[0];
        out[g1 * 3 + 1] = o[4] + bout_s[1];
        out[g1 * 3 + 2] = o[5] + bout_s[2];
        out[g2 * 3 + 0] = o[6] + bout_s[0];
        out[g2 * 3 + 1] = o[7] + bout_s[1];
        out[g2 * 3 + 2] = o[8] + bout_s[2];
        out[g3 * 3 + 0] = o[9] + bout_s[0];
        out[g3 * 3 + 1] = o[10] + bout_s[1];
        out[g3 * 3 + 2] = o[11] + bout_s[2];
    }
}

// ---------------------------------------------------------------------------
// kernel_launch
// ---------------------------------------------------------------------------
extern "C" void kernel_launch(void* const* d_in, const int* in_sizes, int n_in,
                              void* d_out, int out_size) {
    const float* x    = (const float*)d_in[0];   // [262144,3]
    const float* W0   = (const float*)d_in[1];   // [128,3]
    const float* b0   = (const float*)d_in[2];   // [128]
    const float* Wh   = (const float*)d_in[3];   // [7,128,128]
    const float* bh   = (const float*)d_in[4];   // [7,128]
    const float* Wout = (const float*)d_in[5];   // [3,128]
    const float* bout = (const float*)d_in[6];   // [3]
    float* out = (float*)d_out;                  // [262144,3]

    static bool attr_set = false;
    if (!attr_set) {
        cudaFuncSetAttribute(mlp_kernel,
                             cudaFuncAttributeMaxDynamicSharedMemorySize, SMEM_SZ);
        attr_set = true;
    }

    prep_weights_kernel<<<(NHID * 128 * 128 + 255) / 256, 256>>>(Wh);
    mlp_kernel<<<NTILES, THREADS, SMEM_SZ>>>(x, W0, b0, bh, Wout, bout, out);
}